// round 4
// baseline (speedup 1.0000x reference)
#include <cuda_runtime.h>
#include <cstdint>

#define BB 16
#define NP 2048
#define NN (BB*NP)   // 32768 total nodes
#define KNN 30

// ---------------- scratch (device globals; no cudaMalloc allowed) ----------------
__device__ float g_dist[(size_t)NN * NP];   // 268 MB distance matrix
__device__ int   g_idx[NN * KNN];           // kNN indices (within batch)
__device__ float g_n2[NN];                  // squared norms
__device__ float g_feat[NN * 192];          // concat [x1 | x2 | x3]
__device__ float g_h1[NN * 1024];
__device__ float g_h2[NN * 256];
__device__ float g_h3[NN * 128];

// ---------------- helpers ----------------
__device__ __forceinline__ unsigned encf(float f) {
    unsigned u = __float_as_uint(f);
    return (u & 0x80000000u) ? ~u : (u | 0x80000000u);
}
__device__ __forceinline__ float decf(unsigned u) {
    return __uint_as_float((u & 0x80000000u) ? (u ^ 0x80000000u) : ~u);
}

// ---------------- squared norms ----------------
__global__ void sqnorm_kernel(const float* __restrict__ x, int stride, int C) {
    int r = blockIdx.x * blockDim.x + threadIdx.x;
    if (r < NN) {
        const float* p = x + (size_t)r * stride;
        float s = 0.f;
        for (int c = 0; c < C; c++) { float v = p[c]; s += v * v; }
        g_n2[r] = s;
    }
}

// ---------------- distance tiles: D[b,i,j] = n2[j] - 2*dot(x_i,x_j) ----------------
template<int C>
__global__ void dist_kernel(const float* __restrict__ x, int stride) {
    __shared__ float sXi[C * 64];
    __shared__ float sXj[C * 64];
    int b = blockIdx.z;
    int i0 = blockIdx.y * 64, j0 = blockIdx.x * 64;
    int tid = threadIdx.x;
    for (int t = tid; t < 64 * C; t += 256) {
        int r = t / C, c = t % C;
        sXi[c * 64 + r] = x[((size_t)(b * NP + i0 + r)) * stride + c];
        sXj[c * 64 + r] = x[((size_t)(b * NP + j0 + r)) * stride + c];
    }
    __syncthreads();
    int tx = tid & 15, ty = tid >> 4;
    int r0 = 4 * ty, c0 = 4 * tx;
    float acc[4][4] = {};
    #pragma unroll 8
    for (int c = 0; c < C; c++) {
        float4 xj = *(const float4*)&sXj[c * 64 + c0];
        float xi[4];
        #pragma unroll
        for (int i = 0; i < 4; i++) xi[i] = sXi[c * 64 + r0 + i];
        #pragma unroll
        for (int i = 0; i < 4; i++) {
            acc[i][0] += xi[i] * xj.x;
            acc[i][1] += xi[i] * xj.y;
            acc[i][2] += xi[i] * xj.z;
            acc[i][3] += xi[i] * xj.w;
        }
    }
    float4 n2v = *(const float4*)&g_n2[b * NP + j0 + c0];
    #pragma unroll
    for (int i = 0; i < 4; i++) {
        float4 o;
        o.x = n2v.x - 2.f * acc[i][0];
        o.y = n2v.y - 2.f * acc[i][1];
        o.z = n2v.z - 2.f * acc[i][2];
        o.w = n2v.w - 2.f * acc[i][3];
        *(float4*)&g_dist[((size_t)(b * NP + i0 + r0 + i)) * NP + j0 + c0] = o;
    }
}

// ---------------- top-30 smallest per row (iterative argmin extraction) ----------------
__global__ void topk_kernel() {
    __shared__ float sD[NP];
    __shared__ float sRV[8];
    __shared__ int   sRI[8];
    int r = blockIdx.x;
    int tid = threadIdx.x;
    const float* Drow = g_dist + (size_t)r * NP;
    for (int t = tid; t < NP / 4; t += 256)
        ((float4*)sD)[t] = ((const float4*)Drow)[t];
    __syncthreads();
    int lane = tid & 31, w = tid >> 5;
    for (int it = 0; it < KNN; it++) {
        float v = 3.0e38f; int bi = 0x7fffffff;
        for (int j = tid; j < NP; j += 256) {
            float d = sD[j];
            if (d < v) { v = d; bi = j; }
        }
        #pragma unroll
        for (int o = 16; o > 0; o >>= 1) {
            float ov = __shfl_down_sync(0xffffffffu, v, o);
            int   oi = __shfl_down_sync(0xffffffffu, bi, o);
            if (ov < v || (ov == v && oi < bi)) { v = ov; bi = oi; }
        }
        if (lane == 0) { sRV[w] = v; sRI[w] = bi; }
        __syncthreads();
        if (tid == 0) {
            float bv = sRV[0]; int bbw = sRI[0];
            for (int q = 1; q < 8; q++)
                if (sRV[q] < bv || (sRV[q] == bv && sRI[q] < bbw)) { bv = sRV[q]; bbw = sRI[q]; }
            g_idx[r * KNN + it] = bbw;
            sD[bbw] = 3.0e38f;
        }
        __syncthreads();
    }
}

// ---------------- fused EdgeConv: 2 nodes/block, two 64x64x64 smem GEMMs + max ----------------
// h0[e][t] = relu(a_node[t] + sum_c xj[e][c]*W0[CIN+c][t]),  a_node[t] = b0[t] + sum_c xi[c]*(W0[c][t]-W0[CIN+c][t])
// out[node][t] = max_e (sum_u h0[e][u]*W1[u][t]) + b1[t]
template<int CIN>
__global__ __launch_bounds__(256)
void edgeconv_kernel(const float* __restrict__ x, int xstride,
                     const float* __restrict__ w0, const float* __restrict__ b0,
                     const float* __restrict__ w1, const float* __restrict__ b1,
                     float* __restrict__ out, int ostride) {
    extern __shared__ float sm[];
    float* sW0 = sm;                        // 2*CIN*64
    float* sW1 = sW0 + 2 * CIN * 64;        // 4096
    float* sB1 = sW1 + 4096;                // 64
    float* sXI = sB1 + 64;                  // 128
    float* sA  = sXI + 128;                 // 128
    float* sXJ = sA + 128;                  // CIN*64  (layout [c][e], stride 64)
    float* sH0 = sXJ + CIN * 64;            // 4096    (layout [u][e], stride 64)
    unsigned* sOut = (unsigned*)(sH0 + 4096); // 128

    int tid = threadIdx.x;
    int gn0 = blockIdx.x * 2;

    for (int t = tid; t < 2 * CIN * 64; t += 256) sW0[t] = w0[t];
    for (int t = tid; t < 4096; t += 256) sW1[t] = w1[t];
    if (tid < 64) sB1[tid] = b1[tid];
    if (tid < 128) sOut[tid] = 0u;
    for (int t = tid; t < 2 * CIN; t += 256) {
        int nd = t / CIN, c = t % CIN;
        sXI[nd * 64 + c] = x[(size_t)(gn0 + nd) * xstride + c];
    }
    __syncthreads();
    if (tid < 128) {
        int nd = tid >> 6, t = tid & 63;
        float s = b0[t];
        #pragma unroll 8
        for (int c = 0; c < CIN; c++)
            s += sXI[nd * 64 + c] * (sW0[c * 64 + t] - sW0[(CIN + c) * 64 + t]);
        sA[nd * 64 + t] = s;
    }
    // gather neighbors (60 edges, pad to 64 with zeros)
    for (int t = tid; t < 64 * CIN; t += 256) {
        int e = t / CIN, c = t % CIN;
        float v = 0.f;
        if (e < 60) {
            int nd = e / 30, k = e - nd * 30;
            int gn = gn0 + nd, bi = gn >> 11;
            int j = g_idx[gn * KNN + k];
            v = x[((size_t)(bi * NP + j)) * xstride + c];
        }
        sXJ[c * 64 + e] = v;
    }
    __syncthreads();

    int tx = tid & 15, ty = tid >> 4;
    int r0 = 4 * ty, c0 = 4 * tx;

    // stage 1
    float acc[4][4] = {};
    #pragma unroll 8
    for (int c = 0; c < CIN; c++) {
        float xv[4];
        #pragma unroll
        for (int i = 0; i < 4; i++) xv[i] = sXJ[c * 64 + r0 + i];
        float4 wv = *(const float4*)&sW0[(CIN + c) * 64 + c0];
        #pragma unroll
        for (int i = 0; i < 4; i++) {
            acc[i][0] += xv[i] * wv.x;
            acc[i][1] += xv[i] * wv.y;
            acc[i][2] += xv[i] * wv.z;
            acc[i][3] += xv[i] * wv.w;
        }
    }
    #pragma unroll
    for (int i = 0; i < 4; i++) {
        int e = r0 + i;
        int nd = (e < 30) ? 0 : 1;
        #pragma unroll
        for (int j = 0; j < 4; j++) {
            float h = acc[i][j] + sA[nd * 64 + c0 + j];
            sH0[(c0 + j) * 64 + e] = h > 0.f ? h : 0.f;
        }
    }
    __syncthreads();

    // stage 2
    float acc2[4][4] = {};
    #pragma unroll 8
    for (int u = 0; u < 64; u++) {
        float xv[4];
        #pragma unroll
        for (int i = 0; i < 4; i++) xv[i] = sH0[u * 64 + r0 + i];
        float4 wv = *(const float4*)&sW1[u * 64 + c0];
        #pragma unroll
        for (int i = 0; i < 4; i++) {
            acc2[i][0] += xv[i] * wv.x;
            acc2[i][1] += xv[i] * wv.y;
            acc2[i][2] += xv[i] * wv.z;
            acc2[i][3] += xv[i] * wv.w;
        }
    }
    #pragma unroll
    for (int i = 0; i < 4; i++) {
        int e = r0 + i;
        if (e < 60) {
            int nd = e / 30;
            #pragma unroll
            for (int j = 0; j < 4; j++)
                atomicMax(&sOut[nd * 64 + c0 + j], encf(acc2[i][j]));
        }
    }
    __syncthreads();
    if (tid < 128) {
        int nd = tid >> 6, t = tid & 63;
        out[(size_t)(gn0 + nd) * ostride + t] = decf(sOut[nd * 64 + t]) + sB1[t];
    }
}

// ---------------- generic SGEMM: C[M,N] = relu?(A[M,K] @ W[K,N] + bias) ----------------
// 128x64 block tile, 256 threads, 8x4 microtile. M%128==0, N%64==0, K%16==0.
__global__ __launch_bounds__(256)
void sgemm_kernel(const float* __restrict__ A, const float* __restrict__ W,
                  const float* __restrict__ bias, float* __restrict__ C,
                  int M, int Nn, int Kk, int relu) {
    __shared__ float As[16 * 128];
    __shared__ float Bs[16 * 64];
    int tid = threadIdx.x;
    int m0 = blockIdx.y * 128, n0 = blockIdx.x * 64;
    int tx = tid & 15, ty = tid >> 4;
    float acc[8][4] = {};
    for (int k0 = 0; k0 < Kk; k0 += 16) {
        #pragma unroll
        for (int q = 0; q < 2; q++) {
            int fi = tid + q * 256;
            int row = fi >> 2, kq = fi & 3;
            float4 a = *(const float4*)&A[(size_t)(m0 + row) * Kk + k0 + 4 * kq];
            As[(4 * kq + 0) * 128 + row] = a.x;
            As[(4 * kq + 1) * 128 + row] = a.y;
            As[(4 * kq + 2) * 128 + row] = a.z;
            As[(4 * kq + 3) * 128 + row] = a.w;
        }
        {
            int k = tid >> 4, nq = tid & 15;
            float4 bv = *(const float4*)&W[(size_t)(k0 + k) * Nn + n0 + 4 * nq];
            *(float4*)&Bs[k * 64 + 4 * nq] = bv;
        }
        __syncthreads();
        #pragma unroll
        for (int kk = 0; kk < 16; kk++) {
            float4 b4 = *(const float4*)&Bs[kk * 64 + 4 * tx];
            float4 a0 = *(const float4*)&As[kk * 128 + 8 * ty];
            float4 a1 = *(const float4*)&As[kk * 128 + 8 * ty + 4];
            float a8[8] = {a0.x, a0.y, a0.z, a0.w, a1.x, a1.y, a1.z, a1.w};
            #pragma unroll
            for (int i = 0; i < 8; i++) {
                acc[i][0] += a8[i] * b4.x;
                acc[i][1] += a8[i] * b4.y;
                acc[i][2] += a8[i] * b4.z;
                acc[i][3] += a8[i] * b4.w;
            }
        }
        __syncthreads();
    }
    float4 bv = *(const float4*)&bias[n0 + 4 * tx];
    #pragma unroll
    for (int i = 0; i < 8; i++) {
        float4 o;
        o.x = acc[i][0] + bv.x;
        o.y = acc[i][1] + bv.y;
        o.z = acc[i][2] + bv.z;
        o.w = acc[i][3] + bv.w;
        if (relu) {
            o.x = o.x > 0.f ? o.x : 0.f;
            o.y = o.y > 0.f ? o.y : 0.f;
            o.z = o.z > 0.f ? o.z : 0.f;
            o.w = o.w > 0.f ? o.w : 0.f;
        }
        *(float4*)&C[(size_t)(m0 + 8 * ty + i) * Nn + n0 + 4 * tx] = o;
    }
}

// ---------------- final head: out[m,0:3] = h3[m,:] @ fin_w + fin_b ----------------
__global__ void fin_kernel(const float* __restrict__ h3, const float* __restrict__ w,
                           const float* __restrict__ bb, float* __restrict__ out) {
    __shared__ float sw[128 * 3];
    __shared__ float sb[3];
    int tid = threadIdx.x;
    for (int t = tid; t < 384; t += 256) sw[t] = w[t];
    if (tid < 3) sb[tid] = bb[tid];
    __syncthreads();
    int m = blockIdx.x * 256 + tid;
    const float* row = h3 + (size_t)m * 128;
    float s0 = sb[0], s1 = sb[1], s2 = sb[2];
    #pragma unroll 8
    for (int c = 0; c < 128; c++) {
        float v = row[c];
        s0 += v * sw[c * 3 + 0];
        s1 += v * sw[c * 3 + 1];
        s2 += v * sw[c * 3 + 2];
    }
    out[m * 3 + 0] = s0;
    out[m * 3 + 1] = s1;
    out[m * 3 + 2] = s2;
}

// ---------------- launch ----------------
extern "C" void kernel_launch(void* const* d_in, const int* in_sizes, int n_in,
                              void* d_out, int out_size) {
    const float* pos    = (const float*)d_in[0];
    const float* c1_w0  = (const float*)d_in[1];
    const float* c1_b0  = (const float*)d_in[2];
    const float* c1_w1  = (const float*)d_in[3];
    const float* c1_b1  = (const float*)d_in[4];
    const float* c2_w0  = (const float*)d_in[5];
    const float* c2_b0  = (const float*)d_in[6];
    const float* c2_w1  = (const float*)d_in[7];
    const float* c2_b1  = (const float*)d_in[8];
    const float* c3_w0  = (const float*)d_in[9];
    const float* c3_b0  = (const float*)d_in[10];
    const float* c3_w1  = (const float*)d_in[11];
    const float* c3_b1  = (const float*)d_in[12];
    const float* mlp_w0 = (const float*)d_in[13];
    const float* mlp_b0 = (const float*)d_in[14];
    const float* mlp_w1 = (const float*)d_in[15];
    const float* mlp_b1 = (const float*)d_in[16];
    const float* mlp_w2 = (const float*)d_in[17];
    const float* mlp_b2 = (const float*)d_in[18];
    const float* fin_w  = (const float*)d_in[19];
    const float* fin_b  = (const float*)d_in[20];

    float *feat, *h1, *h2, *h3;
    cudaGetSymbolAddress((void**)&feat, g_feat);
    cudaGetSymbolAddress((void**)&h1, g_h1);
    cudaGetSymbolAddress((void**)&h2, g_h2);
    cudaGetSymbolAddress((void**)&h3, g_h3);

    const int smem64 = 20928 * 4;  // edgeconv<64> dynamic smem bytes
    const int smem3  = 9216 * 4;   // edgeconv<3>
    cudaFuncSetAttribute(edgeconv_kernel<64>, cudaFuncAttributeMaxDynamicSharedMemorySize, smem64);
    cudaFuncSetAttribute(edgeconv_kernel<3>,  cudaFuncAttributeMaxDynamicSharedMemorySize, smem3);

    dim3 dgrid(NP / 64, NP / 64, BB);

    // ---- conv1 (pos, C=3) -> feat[:, 0:64]
    sqnorm_kernel<<<NN / 256, 256>>>(pos, 3, 3);
    dist_kernel<3><<<dgrid, 256>>>(pos, 3);
    topk_kernel<<<NN, 256>>>();
    edgeconv_kernel<3><<<NN / 2, 256, smem3>>>(pos, 3, c1_w0, c1_b0, c1_w1, c1_b1, feat + 0, 192);

    // ---- conv2 (x1, C=64) -> feat[:, 64:128]
    sqnorm_kernel<<<NN / 256, 256>>>(feat, 192, 64);
    dist_kernel<64><<<dgrid, 256>>>(feat, 192);
    topk_kernel<<<NN, 256>>>();
    edgeconv_kernel<64><<<NN / 2, 256, smem64>>>(feat, 192, c2_w0, c2_b0, c2_w1, c2_b1, feat + 64, 192);

    // ---- conv3 (x2, C=64) -> feat[:, 128:192]
    sqnorm_kernel<<<NN / 256, 256>>>(feat + 64, 192, 64);
    dist_kernel<64><<<dgrid, 256>>>(feat + 64, 192);
    topk_kernel<<<NN, 256>>>();
    edgeconv_kernel<64><<<NN / 2, 256, smem64>>>(feat + 64, 192, c3_w0, c3_b0, c3_w1, c3_b1, feat + 128, 192);

    // ---- MLP
    sgemm_kernel<<<dim3(1024 / 64, NN / 128), 256>>>(feat, mlp_w0, mlp_b0, h1, NN, 1024, 192, 1);
    sgemm_kernel<<<dim3(256 / 64, NN / 128), 256>>>(h1, mlp_w1, mlp_b1, h2, NN, 256, 1024, 1);
    sgemm_kernel<<<dim3(128 / 64, NN / 128), 256>>>(h2, mlp_w2, mlp_b2, h3, NN, 128, 256, 0);
    fin_kernel<<<NN / 256, 256>>>(h3, fin_w, fin_b, (float*)d_out);
}

// round 5
// speedup vs baseline: 1.1690x; 1.1690x over previous
#include <cuda_runtime.h>
#include <cstdint>

#define BB 16
#define NP 2048
#define NN (BB*NP)   // 32768 total nodes
#define KNN 30

// ---------------- scratch (device globals; no cudaMalloc allowed) ----------------
__device__ int   g_idx[NN * KNN];           // kNN indices (within batch)
__device__ float g_n2[NN];                  // squared norms
__device__ float g_feat[NN * 192];          // concat [x1 | x2 | x3]
__device__ float g_h1[NN * 1024];
__device__ float g_h2[NN * 256];
__device__ float g_h3[NN * 128];

// ---------------- helpers ----------------
__device__ __forceinline__ unsigned encf(float f) {
    unsigned u = __float_as_uint(f);
    return (u & 0x80000000u) ? ~u : (u | 0x80000000u);
}

// ---------------- squared norms ----------------
__global__ void sqnorm_kernel(const float* __restrict__ x, int stride, int C) {
    int r = blockIdx.x * blockDim.x + threadIdx.x;
    if (r < NN) {
        const float* p = x + (size_t)r * stride;
        float s = 0.f;
        for (int c = 0; c < C; c++) { float v = p[c]; s += v * v; }
        g_n2[r] = s;
    }
}

// ---------------- fused dist + top-30 kNN ----------------
// Block: 256 threads, 8 i-rows of one batch. Distances to all 2048 j computed
// into shared (d = n2[j] - 2*dot; row-constant n2[i] dropped), then warp-per-row
// selection: per-lane sorted top-8 in registers + REDUX-min extraction.
template<int C>
__global__ __launch_bounds__(256) void knn_kernel(const float* __restrict__ x, int stride) {
    constexpr int CH = (C >= 32) ? 32 : C;
    extern __shared__ float sm[];
    float* sD  = sm;                 // 8*2048
    float* sXi = sD + 8 * 2048;      // 8*C
    float* sXj = sXi + 8 * C;        // CH*128
    int tid = threadIdx.x;
    int b = blockIdx.y;
    int i0 = blockIdx.x * 8;
    const float* xb = x + (size_t)b * NP * stride;

    for (int t = tid; t < 8 * C; t += 256) {
        int i = t / C, c = t % C;
        sXi[i * C + c] = xb[(size_t)(i0 + i) * stride + c];
    }

    int iw = tid >> 5, lane = tid & 31;
    for (int jt = 0; jt < NP; jt += 128) {
        float a0 = 0.f, a1 = 0.f, a2 = 0.f, a3 = 0.f;
        for (int cc = 0; cc < C; cc += CH) {
            __syncthreads();
            if (C >= 32) {
                #pragma unroll
                for (int q = 0; q < (CH * 128) / 1024; q++) {
                    int fi = tid + 256 * q;
                    int j = fi >> 3, cq = fi & 7;
                    float4 v = *(const float4*)&xb[(size_t)(jt + j) * stride + cc + 4 * cq];
                    sXj[(4 * cq + 0) * 128 + j] = v.x;
                    sXj[(4 * cq + 1) * 128 + j] = v.y;
                    sXj[(4 * cq + 2) * 128 + j] = v.z;
                    sXj[(4 * cq + 3) * 128 + j] = v.w;
                }
            } else {
                for (int t = tid; t < CH * 128; t += 256) {
                    int c = t >> 7, j = t & 127;
                    sXj[c * 128 + j] = xb[(size_t)(jt + j) * stride + cc + c];
                }
            }
            __syncthreads();
            #pragma unroll
            for (int c = 0; c < CH; c++) {
                float xi = sXi[iw * C + cc + c];
                float4 xj = *(const float4*)&sXj[c * 128 + 4 * lane];
                a0 += xi * xj.x; a1 += xi * xj.y; a2 += xi * xj.z; a3 += xi * xj.w;
            }
        }
        float4 n2 = *(const float4*)&g_n2[b * NP + jt + 4 * lane];
        float4 o;
        o.x = n2.x - 2.f * a0; o.y = n2.y - 2.f * a1;
        o.z = n2.z - 2.f * a2; o.w = n2.w - 2.f * a3;
        *(float4*)&sD[iw * 2048 + jt + 4 * lane] = o;
    }
    __syncthreads();

    // ---- selection: warp iw handles row iw ----
    const float* Drow = sD + iw * 2048;
    unsigned long long K8[8];
    #pragma unroll
    for (int q = 0; q < 8; q++) K8[q] = ~0ull;
    for (int t = 0; t < 64; t++) {
        int j = lane + 32 * t;
        unsigned long long key = ((unsigned long long)encf(Drow[j]) << 32) | (unsigned)j;
        if (key < K8[7]) {
            unsigned long long cur = key;
            #pragma unroll
            for (int q = 0; q < 8; q++) {
                unsigned long long a = K8[q];
                unsigned long long mn = a < cur ? a : cur;
                cur = a < cur ? cur : a;
                K8[q] = mn;
            }
        }
    }
    int cnt = 8;
    unsigned long long lastkey = 0;
    int gn = b * NP + i0 + iw;
    for (int it = 0; it < KNN; it++) {
        unsigned hv = (unsigned)(K8[0] >> 32);
        unsigned mv = __reduce_min_sync(0xffffffffu, hv);
        unsigned jc = (hv == mv) ? (unsigned)K8[0] : 0xffffffffu;
        unsigned jmin = __reduce_min_sync(0xffffffffu, jc);
        if (hv == mv && (unsigned)K8[0] == jmin) {
            g_idx[gn * KNN + it] = (int)jmin;
            lastkey = K8[0];
            #pragma unroll
            for (int q = 0; q < 7; q++) K8[q] = K8[q + 1];
            K8[7] = ~0ull;
            if (--cnt == 0) {
                #pragma unroll
                for (int q = 0; q < 8; q++) K8[q] = ~0ull;
                for (int t = 0; t < 64; t++) {
                    int j = lane + 32 * t;
                    unsigned long long key = ((unsigned long long)encf(Drow[j]) << 32) | (unsigned)j;
                    if (key > lastkey && key < K8[7]) {
                        unsigned long long cur = key;
                        #pragma unroll
                        for (int q = 0; q < 8; q++) {
                            unsigned long long a = K8[q];
                            unsigned long long mn = a < cur ? a : cur;
                            cur = a < cur ? cur : a;
                            K8[q] = mn;
                        }
                    }
                }
                cnt = 8;
            }
        }
    }
}

// ---------------- fused EdgeConv: 2 nodes/block, two 64x64x64 smem GEMMs + shfl-max ----------------
// h0[e][t] = relu(a_nd[t] + sum_c xj[e][c]*W0[CIN+c][t]), a_nd[t] = b0[t] + x_i.(W0_top - W0_bot)
// out[nd][t] = max_e (h0[e] @ W1)[t] + b1[t]
// Microtile: tx (lane low 4 bits) -> edge dim, ty -> out-channel dim. All e live in a
// half-warp -> max-aggregation via width-16 shfl reduction (no atomics).
template<int CIN>
__global__ __launch_bounds__(256)
void edgeconv_kernel(const float* __restrict__ x, int xstride,
                     const float* __restrict__ w0, const float* __restrict__ b0,
                     const float* __restrict__ w1, const float* __restrict__ b1,
                     float* __restrict__ out, int ostride) {
    extern __shared__ float sm[];
    float* sW0 = sm;                   // 2*CIN*64
    float* sW1 = sW0 + 2 * CIN * 64;   // 4096
    float* sB1 = sW1 + 4096;           // 64
    float* sXI = sB1 + 64;             // 128
    float* sA  = sXI + 128;            // 128
    float* sXJ = sA + 128;             // CIN*64  ([c][e])
    float* sH0 = sXJ + CIN * 64;       // 4096    ([u][e])

    int tid = threadIdx.x;
    int gn0 = blockIdx.x * 2;

    for (int t = tid; t < 2 * CIN * 64; t += 256) sW0[t] = w0[t];
    for (int t = tid; t < 4096; t += 256) sW1[t] = w1[t];
    if (tid < 64) sB1[tid] = b1[tid];
    for (int t = tid; t < 2 * CIN; t += 256) {
        int nd = t / CIN, c = t % CIN;
        sXI[nd * 64 + c] = x[(size_t)(gn0 + nd) * xstride + c];
    }
    __syncthreads();
    if (tid < 128) {
        int nd = tid >> 6, t = tid & 63;
        float s = b0[t];
        #pragma unroll
        for (int c = 0; c < CIN; c++)
            s += sXI[nd * 64 + c] * (sW0[c * 64 + t] - sW0[(CIN + c) * 64 + t]);
        sA[nd * 64 + t] = s;
    }
    for (int t = tid; t < 64 * CIN; t += 256) {
        int e = t / CIN, c = t % CIN;
        float v = 0.f;
        if (e < 60) {
            int nd = e / 30, k = e - nd * 30;
            int gn = gn0 + nd, bi = gn >> 11;
            int j = g_idx[gn * KNN + k];
            v = x[((size_t)(bi * NP + j)) * xstride + c];
        }
        sXJ[c * 64 + e] = v;
    }
    __syncthreads();

    int tx = tid & 15, ty = tid >> 4;   // e = 4*tx+i, t = 4*ty+j

    // stage 1
    float acc[4][4] = {};
    #pragma unroll
    for (int c = 0; c < CIN; c++) {
        float4 xv = *(const float4*)&sXJ[c * 64 + 4 * tx];
        float4 wv = *(const float4*)&sW0[(CIN + c) * 64 + 4 * ty];
        float xa[4] = {xv.x, xv.y, xv.z, xv.w};
        float wa[4] = {wv.x, wv.y, wv.z, wv.w};
        #pragma unroll
        for (int i = 0; i < 4; i++)
            #pragma unroll
            for (int j = 0; j < 4; j++) acc[i][j] += xa[i] * wa[j];
    }
    #pragma unroll
    for (int j = 0; j < 4; j++) {
        float h[4];
        #pragma unroll
        for (int i = 0; i < 4; i++) {
            int e = 4 * tx + i;
            int nd = (e >= 30) ? 1 : 0;
            float s = acc[i][j] + sA[nd * 64 + 4 * ty + j];
            h[i] = s > 0.f ? s : 0.f;
        }
        *(float4*)&sH0[(4 * ty + j) * 64 + 4 * tx] = make_float4(h[0], h[1], h[2], h[3]);
    }
    __syncthreads();

    // stage 2
    float acc2[4][4] = {};
    #pragma unroll
    for (int u = 0; u < 64; u++) {
        float4 xv = *(const float4*)&sH0[u * 64 + 4 * tx];
        float4 wv = *(const float4*)&sW1[u * 64 + 4 * ty];
        float xa[4] = {xv.x, xv.y, xv.z, xv.w};
        float wa[4] = {wv.x, wv.y, wv.z, wv.w};
        #pragma unroll
        for (int i = 0; i < 4; i++)
            #pragma unroll
            for (int j = 0; j < 4; j++) acc2[i][j] += xa[i] * wa[j];
    }

    // max over edges (half-warp holds all 64 e's)
    float m[2][4];
    #pragma unroll
    for (int nd = 0; nd < 2; nd++)
        #pragma unroll
        for (int j = 0; j < 4; j++) m[nd][j] = -3.4e38f;
    #pragma unroll
    for (int i = 0; i < 4; i++) {
        int e = 4 * tx + i;
        if (e < 60) {
            int nd = (e >= 30) ? 1 : 0;
            #pragma unroll
            for (int j = 0; j < 4; j++) m[nd][j] = fmaxf(m[nd][j], acc2[i][j]);
        }
    }
    #pragma unroll
    for (int o = 8; o >= 1; o >>= 1) {
        #pragma unroll
        for (int nd = 0; nd < 2; nd++)
            #pragma unroll
            for (int j = 0; j < 4; j++)
                m[nd][j] = fmaxf(m[nd][j], __shfl_down_sync(0xffffffffu, m[nd][j], o, 16));
    }
    if (tx == 0) {
        #pragma unroll
        for (int nd = 0; nd < 2; nd++)
            #pragma unroll
            for (int j = 0; j < 4; j++)
                out[(size_t)(gn0 + nd) * ostride + 4 * ty + j] = m[nd][j] + sB1[4 * ty + j];
    }
}

// ---------------- SGEMM: C[M,N] = relu?(A[M,K] @ W[K,N] + bias) ----------------
// 128x128 block tile, 256 threads, 8x8 microtile. M%128==0, N%128==0, K%16==0.
__global__ __launch_bounds__(256)
void sgemm_kernel(const float* __restrict__ A, const float* __restrict__ W,
                  const float* __restrict__ bias, float* __restrict__ C,
                  int M, int Nn, int Kk, int relu) {
    __shared__ float As[16 * 128];
    __shared__ float Bs[16 * 128];
    int tid = threadIdx.x;
    int m0 = blockIdx.y * 128, n0 = blockIdx.x * 128;
    int tx = tid & 15, ty = tid >> 4;
    float acc[8][8] = {};
    for (int k0 = 0; k0 < Kk; k0 += 16) {
        #pragma unroll
        for (int q = 0; q < 2; q++) {
            int fi = tid + 256 * q;
            int row = fi >> 2, kq = fi & 3;
            float4 a = *(const float4*)&A[(size_t)(m0 + row) * Kk + k0 + 4 * kq];
            As[(4 * kq + 0) * 128 + row] = a.x;
            As[(4 * kq + 1) * 128 + row] = a.y;
            As[(4 * kq + 2) * 128 + row] = a.z;
            As[(4 * kq + 3) * 128 + row] = a.w;
        }
        #pragma unroll
        for (int q = 0; q < 2; q++) {
            int fi = tid + 256 * q;
            int k = fi >> 5, nq = fi & 31;
            *(float4*)&Bs[k * 128 + 4 * nq] =
                *(const float4*)&W[(size_t)(k0 + k) * Nn + n0 + 4 * nq];
        }
        __syncthreads();
        #pragma unroll
        for (int kk = 0; kk < 16; kk++) {
            float4 a0 = *(const float4*)&As[kk * 128 + 8 * ty];
            float4 a1 = *(const float4*)&As[kk * 128 + 8 * ty + 4];
            float4 b0 = *(const float4*)&Bs[kk * 128 + 8 * tx];
            float4 b1 = *(const float4*)&Bs[kk * 128 + 8 * tx + 4];
            float aa[8] = {a0.x, a0.y, a0.z, a0.w, a1.x, a1.y, a1.z, a1.w};
            float bb[8] = {b0.x, b0.y, b0.z, b0.w, b1.x, b1.y, b1.z, b1.w};
            #pragma unroll
            for (int i = 0; i < 8; i++)
                #pragma unroll
                for (int j = 0; j < 8; j++) acc[i][j] += aa[i] * bb[j];
        }
        __syncthreads();
    }
    float4 bv0 = *(const float4*)&bias[n0 + 8 * tx];
    float4 bv1 = *(const float4*)&bias[n0 + 8 * tx + 4];
    float bb[8] = {bv0.x, bv0.y, bv0.z, bv0.w, bv1.x, bv1.y, bv1.z, bv1.w};
    #pragma unroll
    for (int i = 0; i < 8; i++) {
        float o[8];
        #pragma unroll
        for (int j = 0; j < 8; j++) {
            float v = acc[i][j] + bb[j];
            o[j] = (relu && v < 0.f) ? 0.f : v;
        }
        *(float4*)&C[(size_t)(m0 + 8 * ty + i) * Nn + n0 + 8 * tx] =
            make_float4(o[0], o[1], o[2], o[3]);
        *(float4*)&C[(size_t)(m0 + 8 * ty + i) * Nn + n0 + 8 * tx + 4] =
            make_float4(o[4], o[5], o[6], o[7]);
    }
}

// ---------------- final head: out[m,0:3] = h3[m,:] @ fin_w + fin_b ----------------
__global__ void fin_kernel(const float* __restrict__ h3, const float* __restrict__ w,
                           const float* __restrict__ bb, float* __restrict__ out) {
    __shared__ float sw[128 * 3];
    __shared__ float sb[3];
    int tid = threadIdx.x;
    for (int t = tid; t < 384; t += 256) sw[t] = w[t];
    if (tid < 3) sb[tid] = bb[tid];
    __syncthreads();
    int m = blockIdx.x * 256 + tid;
    const float* row = h3 + (size_t)m * 128;
    float s0 = sb[0], s1 = sb[1], s2 = sb[2];
    #pragma unroll 8
    for (int c = 0; c < 128; c++) {
        float v = row[c];
        s0 += v * sw[c * 3 + 0];
        s1 += v * sw[c * 3 + 1];
        s2 += v * sw[c * 3 + 2];
    }
    out[m * 3 + 0] = s0;
    out[m * 3 + 1] = s1;
    out[m * 3 + 2] = s2;
}

// ---------------- launch ----------------
extern "C" void kernel_launch(void* const* d_in, const int* in_sizes, int n_in,
                              void* d_out, int out_size) {
    const float* pos    = (const float*)d_in[0];
    const float* c1_w0  = (const float*)d_in[1];
    const float* c1_b0  = (const float*)d_in[2];
    const float* c1_w1  = (const float*)d_in[3];
    const float* c1_b1  = (const float*)d_in[4];
    const float* c2_w0  = (const float*)d_in[5];
    const float* c2_b0  = (const float*)d_in[6];
    const float* c2_w1  = (const float*)d_in[7];
    const float* c2_b1  = (const float*)d_in[8];
    const float* c3_w0  = (const float*)d_in[9];
    const float* c3_b0  = (const float*)d_in[10];
    const float* c3_w1  = (const float*)d_in[11];
    const float* c3_b1  = (const float*)d_in[12];
    const float* mlp_w0 = (const float*)d_in[13];
    const float* mlp_b0 = (const float*)d_in[14];
    const float* mlp_w1 = (const float*)d_in[15];
    const float* mlp_b1 = (const float*)d_in[16];
    const float* mlp_w2 = (const float*)d_in[17];
    const float* mlp_b2 = (const float*)d_in[18];
    const float* fin_w  = (const float*)d_in[19];
    const float* fin_b  = (const float*)d_in[20];

    float *feat, *h1, *h2, *h3;
    cudaGetSymbolAddress((void**)&feat, g_feat);
    cudaGetSymbolAddress((void**)&h1, g_h1);
    cudaGetSymbolAddress((void**)&h2, g_h2);
    cudaGetSymbolAddress((void**)&h3, g_h3);

    // dynamic smem sizes
    const int smemKNN3  = (8 * 2048 + 8 * 3 + 3 * 128) * 4;
    const int smemKNN64 = (8 * 2048 + 8 * 64 + 32 * 128) * 4;
    const int smemEC3   = (2 * 3 * 64 + 4096 + 64 + 128 + 128 + 3 * 64 + 4096) * 4;
    const int smemEC64  = (2 * 64 * 64 + 4096 + 64 + 128 + 128 + 64 * 64 + 4096) * 4;
    cudaFuncSetAttribute(knn_kernel<3>,  cudaFuncAttributeMaxDynamicSharedMemorySize, smemKNN3);
    cudaFuncSetAttribute(knn_kernel<64>, cudaFuncAttributeMaxDynamicSharedMemorySize, smemKNN64);
    cudaFuncSetAttribute(edgeconv_kernel<3>,  cudaFuncAttributeMaxDynamicSharedMemorySize, smemEC3);
    cudaFuncSetAttribute(edgeconv_kernel<64>, cudaFuncAttributeMaxDynamicSharedMemorySize, smemEC64);

    dim3 kgrid(NP / 8, BB);

    // ---- conv1 (pos, C=3) -> feat[:, 0:64]
    sqnorm_kernel<<<NN / 256, 256>>>(pos, 3, 3);
    knn_kernel<3><<<kgrid, 256, smemKNN3>>>(pos, 3);
    edgeconv_kernel<3><<<NN / 2, 256, smemEC3>>>(pos, 3, c1_w0, c1_b0, c1_w1, c1_b1, feat + 0, 192);

    // ---- conv2 (x1, C=64) -> feat[:, 64:128]
    sqnorm_kernel<<<NN / 256, 256>>>(feat, 192, 64);
    knn_kernel<64><<<kgrid, 256, smemKNN64>>>(feat, 192);
    edgeconv_kernel<64><<<NN / 2, 256, smemEC64>>>(feat, 192, c2_w0, c2_b0, c2_w1, c2_b1, feat + 64, 192);

    // ---- conv3 (x2, C=64) -> feat[:, 128:192]
    sqnorm_kernel<<<NN / 256, 256>>>(feat + 64, 192, 64);
    knn_kernel<64><<<kgrid, 256, smemKNN64>>>(feat + 64, 192);
    edgeconv_kernel<64><<<NN / 2, 256, smemEC64>>>(feat + 64, 192, c3_w0, c3_b0, c3_w1, c3_b1, feat + 128, 192);

    // ---- MLP
    sgemm_kernel<<<dim3(1024 / 128, NN / 128), 256>>>(feat, mlp_w0, mlp_b0, h1, NN, 1024, 192, 1);
    sgemm_kernel<<<dim3(256 / 128, NN / 128), 256>>>(h1, mlp_w1, mlp_b1, h2, NN, 256, 1024, 1);
    sgemm_kernel<<<dim3(128 / 128, NN / 128), 256>>>(h2, mlp_w2, mlp_b2, h3, NN, 128, 256, 0);
    fin_kernel<<<NN / 256, 256>>>(h3, fin_w, fin_b, (float*)d_out);
}

// round 6
// speedup vs baseline: 1.2405x; 1.0612x over previous
#include <cuda_runtime.h>
#include <cstdint>

#define BB 16
#define NP 2048
#define NN (BB*NP)   // 32768 total nodes
#define KNN 30

typedef unsigned long long u64;

// ---------------- scratch (device globals; no cudaMalloc allowed) ----------------
__device__ int   g_idx[NN * KNN];           // kNN indices (within batch)
__device__ float g_n2[NN];                  // squared norms
__device__ float g_feat[NN * 192];          // concat [x1 | x2 | x3]
__device__ float g_h1[NN * 1024];
__device__ float g_h2[NN * 256];
__device__ float g_h3[NN * 128];

// ---------------- helpers ----------------
__device__ __forceinline__ unsigned encf(float f) {
    unsigned u = __float_as_uint(f);
    return (u & 0x80000000u) ? ~u : (u | 0x80000000u);
}
// packed fp32x2 (sm_100+): one instruction, two exact fp32 FMAs
__device__ __forceinline__ u64 splat2(float v) {
    u64 r; asm("mov.b64 %0, {%1, %1};" : "=l"(r) : "f"(v)); return r;
}
__device__ __forceinline__ u64 ffma2(u64 a, u64 b, u64 c) {
    u64 d; asm("fma.rn.f32x2 %0, %1, %2, %3;" : "=l"(d) : "l"(a), "l"(b), "l"(c)); return d;
}
__device__ __forceinline__ float2 unpack2(u64 v) {
    float2 r; asm("mov.b64 {%0, %1}, %2;" : "=f"(r.x), "=f"(r.y) : "l"(v)); return r;
}

// ---------------- squared norms ----------------
__global__ void sqnorm_kernel(const float* __restrict__ x, int stride, int C) {
    int r = blockIdx.x * blockDim.x + threadIdx.x;
    if (r < NN) {
        const float* p = x + (size_t)r * stride;
        float s = 0.f;
        for (int c = 0; c < C; c++) { float v = p[c]; s += v * v; }
        g_n2[r] = s;
    }
}

// ---------------- fused dist + top-30 kNN ----------------
// Block: 256 threads, 8 i-rows of one batch. Distances to all 2048 j computed
// into shared (d = n2[j] - 2*dot; row-constant n2[i] dropped), then warp-per-row
// selection: per-lane sorted top-8 in registers + REDUX-min extraction.
template<int C>
__global__ __launch_bounds__(256) void knn_kernel(const float* __restrict__ x, int stride) {
    constexpr int CH = (C >= 32) ? 32 : C;
    extern __shared__ float sm[];
    float* sD  = sm;                 // 8*2048
    float* sXi = sD + 8 * 2048;      // 8*C
    float* sXj = sXi + 8 * C;        // CH*128
    int tid = threadIdx.x;
    int b = blockIdx.y;
    int i0 = blockIdx.x * 8;
    const float* xb = x + (size_t)b * NP * stride;

    for (int t = tid; t < 8 * C; t += 256) {
        int i = t / C, c = t % C;
        sXi[i * C + c] = xb[(size_t)(i0 + i) * stride + c];
    }

    int iw = tid >> 5, lane = tid & 31;
    for (int jt = 0; jt < NP; jt += 128) {
        u64 ap0 = 0ull, ap1 = 0ull;
        for (int cc = 0; cc < C; cc += CH) {
            __syncthreads();
            if (C >= 32) {
                #pragma unroll
                for (int q = 0; q < (CH * 128) / 1024; q++) {
                    int fi = tid + 256 * q;
                    int j = fi >> 3, cq = fi & 7;
                    float4 v = *(const float4*)&xb[(size_t)(jt + j) * stride + cc + 4 * cq];
                    sXj[(4 * cq + 0) * 128 + j] = v.x;
                    sXj[(4 * cq + 1) * 128 + j] = v.y;
                    sXj[(4 * cq + 2) * 128 + j] = v.z;
                    sXj[(4 * cq + 3) * 128 + j] = v.w;
                }
            } else {
                for (int t = tid; t < CH * 128; t += 256) {
                    int c = t >> 7, j = t & 127;
                    sXj[c * 128 + j] = xb[(size_t)(jt + j) * stride + cc + c];
                }
            }
            __syncthreads();
            #pragma unroll
            for (int c = 0; c < CH; c++) {
                u64 xs = splat2(sXi[iw * C + cc + c]);
                ulonglong2 xj = *(const ulonglong2*)&sXj[c * 128 + 4 * lane];
                ap0 = ffma2(xs, xj.x, ap0);
                ap1 = ffma2(xs, xj.y, ap1);
            }
        }
        float2 p0 = unpack2(ap0), p1 = unpack2(ap1);
        float4 n2 = *(const float4*)&g_n2[b * NP + jt + 4 * lane];
        float4 o;
        o.x = n2.x - 2.f * p0.x; o.y = n2.y - 2.f * p0.y;
        o.z = n2.z - 2.f * p1.x; o.w = n2.w - 2.f * p1.y;
        *(float4*)&sD[iw * 2048 + jt + 4 * lane] = o;
    }
    __syncthreads();

    // ---- selection: warp iw handles row iw ----
    const float* Drow = sD + iw * 2048;
    u64 K8[8];
    #pragma unroll
    for (int q = 0; q < 8; q++) K8[q] = ~0ull;
    for (int t = 0; t < 64; t++) {
        int j = lane + 32 * t;
        u64 key = ((u64)encf(Drow[j]) << 32) | (unsigned)j;
        if (key < K8[7]) {
            u64 cur = key;
            #pragma unroll
            for (int q = 0; q < 8; q++) {
                u64 a = K8[q];
                u64 mn = a < cur ? a : cur;
                cur = a < cur ? cur : a;
                K8[q] = mn;
            }
        }
    }
    int cnt = 8;
    u64 lastkey = 0;
    int gn = b * NP + i0 + iw;
    for (int it = 0; it < KNN; it++) {
        unsigned hv = (unsigned)(K8[0] >> 32);
        unsigned mv = __reduce_min_sync(0xffffffffu, hv);
        unsigned jc = (hv == mv) ? (unsigned)K8[0] : 0xffffffffu;
        unsigned jmin = __reduce_min_sync(0xffffffffu, jc);
        if (hv == mv && (unsigned)K8[0] == jmin) {
            g_idx[gn * KNN + it] = (int)jmin;
            lastkey = K8[0];
            #pragma unroll
            for (int q = 0; q < 7; q++) K8[q] = K8[q + 1];
            K8[7] = ~0ull;
            if (--cnt == 0) {
                #pragma unroll
                for (int q = 0; q < 8; q++) K8[q] = ~0ull;
                for (int t = 0; t < 64; t++) {
                    int j = lane + 32 * t;
                    u64 key = ((u64)encf(Drow[j]) << 32) | (unsigned)j;
                    if (key > lastkey && key < K8[7]) {
                        u64 cur = key;
                        #pragma unroll
                        for (int q = 0; q < 8; q++) {
                            u64 a = K8[q];
                            u64 mn = a < cur ? a : cur;
                            cur = a < cur ? cur : a;
                            K8[q] = mn;
                        }
                    }
                }
                cnt = 8;
            }
        }
    }
}

// ---------------- fused EdgeConv: 2 nodes/block, two 64x64x64 smem GEMMs + shfl-max ----------------
template<int CIN>
__global__ __launch_bounds__(256)
void edgeconv_kernel(const float* __restrict__ x, int xstride,
                     const float* __restrict__ w0, const float* __restrict__ b0,
                     const float* __restrict__ w1, const float* __restrict__ b1,
                     float* __restrict__ out, int ostride) {
    extern __shared__ float sm[];
    float* sW0 = sm;                   // 2*CIN*64
    float* sW1 = sW0 + 2 * CIN * 64;   // 4096
    float* sB1 = sW1 + 4096;           // 64
    float* sXI = sB1 + 64;             // 128
    float* sA  = sXI + 128;            // 128
    float* sXJ = sA + 128;             // CIN*64  ([c][e])
    float* sH0 = sXJ + CIN * 64;       // 4096    ([u][e])

    int tid = threadIdx.x;
    int gn0 = blockIdx.x * 2;

    for (int t = tid; t < 2 * CIN * 64; t += 256) sW0[t] = w0[t];
    for (int t = tid; t < 4096; t += 256) sW1[t] = w1[t];
    if (tid < 64) sB1[tid] = b1[tid];
    for (int t = tid; t < 2 * CIN; t += 256) {
        int nd = t / CIN, c = t % CIN;
        sXI[nd * 64 + c] = x[(size_t)(gn0 + nd) * xstride + c];
    }
    __syncthreads();
    if (tid < 128) {
        int nd = tid >> 6, t = tid & 63;
        float s = b0[t];
        #pragma unroll
        for (int c = 0; c < CIN; c++)
            s += sXI[nd * 64 + c] * (sW0[c * 64 + t] - sW0[(CIN + c) * 64 + t]);
        sA[nd * 64 + t] = s;
    }
    for (int t = tid; t < 64 * CIN; t += 256) {
        int e = t / CIN, c = t % CIN;
        float v = 0.f;
        if (e < 60) {
            int nd = e / 30, k = e - nd * 30;
            int gn = gn0 + nd, bi = gn >> 11;
            int j = g_idx[gn * KNN + k];
            v = x[((size_t)(bi * NP + j)) * xstride + c];
        }
        sXJ[c * 64 + e] = v;
    }
    __syncthreads();

    int tx = tid & 15, ty = tid >> 4;   // e = 4*tx+i, t = 4*ty+j

    // stage 1 (packed along output channel j)
    u64 acc[4][2] = {};
    #pragma unroll
    for (int c = 0; c < CIN; c++) {
        float4 xv = *(const float4*)&sXJ[c * 64 + 4 * tx];
        ulonglong2 wq = *(const ulonglong2*)&sW0[(CIN + c) * 64 + 4 * ty];
        u64 xp[4] = {splat2(xv.x), splat2(xv.y), splat2(xv.z), splat2(xv.w)};
        #pragma unroll
        for (int i = 0; i < 4; i++) {
            acc[i][0] = ffma2(xp[i], wq.x, acc[i][0]);
            acc[i][1] = ffma2(xp[i], wq.y, acc[i][1]);
        }
    }
    float accf[4][4];
    #pragma unroll
    for (int i = 0; i < 4; i++) {
        float2 l0 = unpack2(acc[i][0]), l1 = unpack2(acc[i][1]);
        accf[i][0] = l0.x; accf[i][1] = l0.y; accf[i][2] = l1.x; accf[i][3] = l1.y;
    }
    #pragma unroll
    for (int j = 0; j < 4; j++) {
        float h[4];
        #pragma unroll
        for (int i = 0; i < 4; i++) {
            int e = 4 * tx + i;
            int nd = (e >= 30) ? 1 : 0;
            float s = accf[i][j] + sA[nd * 64 + 4 * ty + j];
            h[i] = s > 0.f ? s : 0.f;
        }
        *(float4*)&sH0[(4 * ty + j) * 64 + 4 * tx] = make_float4(h[0], h[1], h[2], h[3]);
    }
    __syncthreads();

    // stage 2
    u64 acc2[4][2] = {};
    #pragma unroll
    for (int u = 0; u < 64; u++) {
        float4 xv = *(const float4*)&sH0[u * 64 + 4 * tx];
        ulonglong2 wq = *(const ulonglong2*)&sW1[u * 64 + 4 * ty];
        u64 xp[4] = {splat2(xv.x), splat2(xv.y), splat2(xv.z), splat2(xv.w)};
        #pragma unroll
        for (int i = 0; i < 4; i++) {
            acc2[i][0] = ffma2(xp[i], wq.x, acc2[i][0]);
            acc2[i][1] = ffma2(xp[i], wq.y, acc2[i][1]);
        }
    }
    float acc2f[4][4];
    #pragma unroll
    for (int i = 0; i < 4; i++) {
        float2 l0 = unpack2(acc2[i][0]), l1 = unpack2(acc2[i][1]);
        acc2f[i][0] = l0.x; acc2f[i][1] = l0.y; acc2f[i][2] = l1.x; acc2f[i][3] = l1.y;
    }

    // max over edges (half-warp holds all 64 e's)
    float m[2][4];
    #pragma unroll
    for (int nd = 0; nd < 2; nd++)
        #pragma unroll
        for (int j = 0; j < 4; j++) m[nd][j] = -3.4e38f;
    #pragma unroll
    for (int i = 0; i < 4; i++) {
        int e = 4 * tx + i;
        if (e < 60) {
            int nd = (e >= 30) ? 1 : 0;
            #pragma unroll
            for (int j = 0; j < 4; j++) m[nd][j] = fmaxf(m[nd][j], acc2f[i][j]);
        }
    }
    #pragma unroll
    for (int o = 8; o >= 1; o >>= 1) {
        #pragma unroll
        for (int nd = 0; nd < 2; nd++)
            #pragma unroll
            for (int j = 0; j < 4; j++)
                m[nd][j] = fmaxf(m[nd][j], __shfl_down_sync(0xffffffffu, m[nd][j], o, 16));
    }
    if (tx == 0) {
        #pragma unroll
        for (int nd = 0; nd < 2; nd++)
            #pragma unroll
            for (int j = 0; j < 4; j++)
                out[(size_t)(gn0 + nd) * ostride + 4 * ty + j] = m[nd][j] + sB1[4 * ty + j];
    }
}

// ---------------- SGEMM: C[M,N] = relu?(A[M,K] @ W[K,N] + bias) ----------------
// 128x128 block tile, 256 threads, 8x8 microtile, f32x2 packed FMA.
__global__ __launch_bounds__(256)
void sgemm_kernel(const float* __restrict__ A, const float* __restrict__ W,
                  const float* __restrict__ bias, float* __restrict__ C,
                  int M, int Nn, int Kk, int relu) {
    __shared__ float As[16 * 128];
    __shared__ float Bs[16 * 128];
    int tid = threadIdx.x;
    int m0 = blockIdx.y * 128, n0 = blockIdx.x * 128;
    int tx = tid & 15, ty = tid >> 4;
    u64 acc[8][4] = {};
    for (int k0 = 0; k0 < Kk; k0 += 16) {
        #pragma unroll
        for (int q = 0; q < 2; q++) {
            int fi = tid + 256 * q;
            int row = fi >> 2, kq = fi & 3;
            float4 a = *(const float4*)&A[(size_t)(m0 + row) * Kk + k0 + 4 * kq];
            As[(4 * kq + 0) * 128 + row] = a.x;
            As[(4 * kq + 1) * 128 + row] = a.y;
            As[(4 * kq + 2) * 128 + row] = a.z;
            As[(4 * kq + 3) * 128 + row] = a.w;
        }
        #pragma unroll
        for (int q = 0; q < 2; q++) {
            int fi = tid + 256 * q;
            int k = fi >> 5, nq = fi & 31;
            *(float4*)&Bs[k * 128 + 4 * nq] =
                *(const float4*)&W[(size_t)(k0 + k) * Nn + n0 + 4 * nq];
        }
        __syncthreads();
        #pragma unroll
        for (int kk = 0; kk < 16; kk++) {
            float4 a0 = *(const float4*)&As[kk * 128 + 8 * ty];
            float4 a1 = *(const float4*)&As[kk * 128 + 8 * ty + 4];
            ulonglong2 bq0 = *(const ulonglong2*)&Bs[kk * 128 + 8 * tx];
            ulonglong2 bq1 = *(const ulonglong2*)&Bs[kk * 128 + 8 * tx + 4];
            u64 bp[4] = {bq0.x, bq0.y, bq1.x, bq1.y};
            u64 ap[8] = {splat2(a0.x), splat2(a0.y), splat2(a0.z), splat2(a0.w),
                         splat2(a1.x), splat2(a1.y), splat2(a1.z), splat2(a1.w)};
            #pragma unroll
            for (int i = 0; i < 8; i++)
                #pragma unroll
                for (int jp = 0; jp < 4; jp++)
                    acc[i][jp] = ffma2(ap[i], bp[jp], acc[i][jp]);
        }
        __syncthreads();
    }
    float4 bv0 = *(const float4*)&bias[n0 + 8 * tx];
    float4 bv1 = *(const float4*)&bias[n0 + 8 * tx + 4];
    float bb[8] = {bv0.x, bv0.y, bv0.z, bv0.w, bv1.x, bv1.y, bv1.z, bv1.w};
    #pragma unroll
    for (int i = 0; i < 8; i++) {
        float o[8];
        #pragma unroll
        for (int jp = 0; jp < 4; jp++) {
            float2 l = unpack2(acc[i][jp]);
            o[2 * jp] = l.x; o[2 * jp + 1] = l.y;
        }
        #pragma unroll
        for (int j = 0; j < 8; j++) {
            float v = o[j] + bb[j];
            o[j] = (relu && v < 0.f) ? 0.f : v;
        }
        *(float4*)&C[(size_t)(m0 + 8 * ty + i) * Nn + n0 + 8 * tx] =
            make_float4(o[0], o[1], o[2], o[3]);
        *(float4*)&C[(size_t)(m0 + 8 * ty + i) * Nn + n0 + 8 * tx + 4] =
            make_float4(o[4], o[5], o[6], o[7]);
    }
}

// ---------------- final head: out[m,0:3] = h3[m,:] @ fin_w + fin_b ----------------
__global__ void fin_kernel(const float* __restrict__ h3, const float* __restrict__ w,
                           const float* __restrict__ bb, float* __restrict__ out) {
    __shared__ float sw[128 * 3];
    __shared__ float sb[3];
    int tid = threadIdx.x;
    for (int t = tid; t < 384; t += 256) sw[t] = w[t];
    if (tid < 3) sb[tid] = bb[tid];
    __syncthreads();
    int m = blockIdx.x * 256 + tid;
    const float* row = h3 + (size_t)m * 128;
    float s0 = sb[0], s1 = sb[1], s2 = sb[2];
    #pragma unroll 8
    for (int c = 0; c < 128; c++) {
        float v = row[c];
        s0 += v * sw[c * 3 + 0];
        s1 += v * sw[c * 3 + 1];
        s2 += v * sw[c * 3 + 2];
    }
    out[m * 3 + 0] = s0;
    out[m * 3 + 1] = s1;
    out[m * 3 + 2] = s2;
}

// ---------------- launch ----------------
extern "C" void kernel_launch(void* const* d_in, const int* in_sizes, int n_in,
                              void* d_out, int out_size) {
    const float* pos    = (const float*)d_in[0];
    const float* c1_w0  = (const float*)d_in[1];
    const float* c1_b0  = (const float*)d_in[2];
    const float* c1_w1  = (const float*)d_in[3];
    const float* c1_b1  = (const float*)d_in[4];
    const float* c2_w0  = (const float*)d_in[5];
    const float* c2_b0  = (const float*)d_in[6];
    const float* c2_w1  = (const float*)d_in[7];
    const float* c2_b1  = (const float*)d_in[8];
    const float* c3_w0  = (const float*)d_in[9];
    const float* c3_b0  = (const float*)d_in[10];
    const float* c3_w1  = (const float*)d_in[11];
    const float* c3_b1  = (const float*)d_in[12];
    const float* mlp_w0 = (const float*)d_in[13];
    const float* mlp_b0 = (const float*)d_in[14];
    const float* mlp_w1 = (const float*)d_in[15];
    const float* mlp_b1 = (const float*)d_in[16];
    const float* mlp_w2 = (const float*)d_in[17];
    const float* mlp_b2 = (const float*)d_in[18];
    const float* fin_w  = (const float*)d_in[19];
    const float* fin_b  = (const float*)d_in[20];

    float *feat, *h1, *h2, *h3;
    cudaGetSymbolAddress((void**)&feat, g_feat);
    cudaGetSymbolAddress((void**)&h1, g_h1);
    cudaGetSymbolAddress((void**)&h2, g_h2);
    cudaGetSymbolAddress((void**)&h3, g_h3);

    // dynamic smem sizes
    const int smemKNN3  = (8 * 2048 + 8 * 3 + 3 * 128) * 4;
    const int smemKNN64 = (8 * 2048 + 8 * 64 + 32 * 128) * 4;
    const int smemEC3   = (2 * 3 * 64 + 4096 + 64 + 128 + 128 + 3 * 64 + 4096) * 4;
    const int smemEC64  = (2 * 64 * 64 + 4096 + 64 + 128 + 128 + 64 * 64 + 4096) * 4;
    cudaFuncSetAttribute(knn_kernel<3>,  cudaFuncAttributeMaxDynamicSharedMemorySize, smemKNN3);
    cudaFuncSetAttribute(knn_kernel<64>, cudaFuncAttributeMaxDynamicSharedMemorySize, smemKNN64);
    cudaFuncSetAttribute(edgeconv_kernel<3>,  cudaFuncAttributeMaxDynamicSharedMemorySize, smemEC3);
    cudaFuncSetAttribute(edgeconv_kernel<64>, cudaFuncAttributeMaxDynamicSharedMemorySize, smemEC64);

    dim3 kgrid(NP / 8, BB);

    // ---- conv1 (pos, C=3) -> feat[:, 0:64]
    sqnorm_kernel<<<NN / 256, 256>>>(pos, 3, 3);
    knn_kernel<3><<<kgrid, 256, smemKNN3>>>(pos, 3);
    edgeconv_kernel<3><<<NN / 2, 256, smemEC3>>>(pos, 3, c1_w0, c1_b0, c1_w1, c1_b1, feat + 0, 192);

    // ---- conv2 (x1, C=64) -> feat[:, 64:128]
    sqnorm_kernel<<<NN / 256, 256>>>(feat, 192, 64);
    knn_kernel<64><<<kgrid, 256, smemKNN64>>>(feat, 192);
    edgeconv_kernel<64><<<NN / 2, 256, smemEC64>>>(feat, 192, c2_w0, c2_b0, c2_w1, c2_b1, feat + 64, 192);

    // ---- conv3 (x2, C=64) -> feat[:, 128:192]
    sqnorm_kernel<<<NN / 256, 256>>>(feat + 64, 192, 64);
    knn_kernel<64><<<kgrid, 256, smemKNN64>>>(feat + 64, 192);
    edgeconv_kernel<64><<<NN / 2, 256, smemEC64>>>(feat + 64, 192, c3_w0, c3_b0, c3_w1, c3_b1, feat + 128, 192);

    // ---- MLP
    sgemm_kernel<<<dim3(1024 / 128, NN / 128), 256>>>(feat, mlp_w0, mlp_b0, h1, NN, 1024, 192, 1);
    sgemm_kernel<<<dim3(256 / 128, NN / 128), 256>>>(h1, mlp_w1, mlp_b1, h2, NN, 256, 1024, 1);
    sgemm_kernel<<<dim3(128 / 128, NN / 128), 256>>>(h2, mlp_w2, mlp_b2, h3, NN, 128, 256, 0);
    fin_kernel<<<NN / 256, 256>>>(h3, fin_w, fin_b, (float*)d_out);
}

// round 7
// speedup vs baseline: 1.5197x; 1.2251x over previous
#include <cuda_runtime.h>
#include <cstdint>

#define BB 16
#define NP 2048
#define NN (BB*NP)   // 32768 total nodes
#define KNN 30

typedef unsigned long long u64;

// ---------------- scratch (device globals; no cudaMalloc allowed) ----------------
__device__ int   g_idx[NN * KNN];           // kNN indices (within batch)
__device__ float g_n2[NN];                  // squared norms
__device__ float g_xt[BB * 64 * NP];        // transposed features [b][c][j]
__device__ float g_feat[NN * 192];          // concat [x1 | x2 | x3]
__device__ float g_h1[NN * 1024];
__device__ float g_h2[NN * 256];
__device__ float g_h3[NN * 128];

// ---------------- helpers ----------------
__device__ __forceinline__ unsigned encf(float f) {
    unsigned u = __float_as_uint(f);
    return (u & 0x80000000u) ? ~u : (u | 0x80000000u);
}
// packed fp32x2 (sm_100+): one instruction, two exact fp32 FMAs
__device__ __forceinline__ u64 splat2(float v) {
    u64 r; asm("mov.b64 %0, {%1, %1};" : "=l"(r) : "f"(v)); return r;
}
__device__ __forceinline__ u64 ffma2(u64 a, u64 b, u64 c) {
    u64 d; asm("fma.rn.f32x2 %0, %1, %2, %3;" : "=l"(d) : "l"(a), "l"(b), "l"(c)); return d;
}
__device__ __forceinline__ float2 unpack2(u64 v) {
    float2 r; asm("mov.b64 {%0, %1}, %2;" : "=f"(r.x), "=f"(r.y) : "l"(v)); return r;
}

// ---------------- transpose (+ squared norms) ----------------
__global__ void xpose3_kernel(const float* __restrict__ x, float* __restrict__ xt) {
    int g = blockIdx.x * blockDim.x + threadIdx.x;
    if (g < NN) {
        int b = g >> 11, j = g & (NP - 1);
        float a = x[g * 3], bv = x[g * 3 + 1], c = x[g * 3 + 2];
        float* xtb = xt + (size_t)b * 3 * NP;
        xtb[j] = a; xtb[NP + j] = bv; xtb[2 * NP + j] = c;
        float s = 0.f; s += a * a; s += bv * bv; s += c * c;
        g_n2[g] = s;
    }
}

__global__ __launch_bounds__(256)
void xpose64_kernel(const float* __restrict__ x, int stride, float* __restrict__ xt) {
    __shared__ float s[32][65];
    int b = blockIdx.y, j0 = blockIdx.x * 32, tid = threadIdx.x;
    const float* xb = x + (size_t)b * NP * stride;
    for (int t = tid; t < 32 * 64; t += 256) {
        int j = t >> 6, c = t & 63;
        s[j][c] = xb[(size_t)(j0 + j) * stride + c];
    }
    __syncthreads();
    float* xtb = xt + (size_t)b * 64 * NP;
    for (int t = tid; t < 32 * 64; t += 256) {
        int c = t >> 5, j = t & 31;
        xtb[(size_t)c * NP + j0 + j] = s[j][c];
    }
    if (tid < 32) {
        float acc = 0.f;
        #pragma unroll
        for (int c = 0; c < 64; c++) { float v = s[tid][c]; acc += v * v; }
        g_n2[b * NP + j0 + tid] = acc;
    }
}

// ---------------- fused dist + select scan ----------------
// Computes d[j] = n2[j] - 2*dot(x_i, x_j) for all j from transposed features,
// inserting (key = enc(d)<<32 | j) into the lane's register-resident sorted
// top-8 whenever lastkey < key < K8[7].
template<int C>
__device__ __forceinline__ void knn_scan(const float* __restrict__ xb,
                                         const float* __restrict__ xi,
                                         const float* __restrict__ n2b,
                                         int lane, u64* K8, u64 lastkey) {
    for (int jt = 0; jt < NP; jt += 256) {
        u64 a00 = 0ull, a01 = 0ull, a10 = 0ull, a11 = 0ull;
        #pragma unroll
        for (int c = 0; c < C; c++) {
            u64 xs = splat2(xi[c]);
            const float* col = xb + (size_t)c * NP + jt + 4 * lane;
            ulonglong2 q0 = *(const ulonglong2*)col;
            ulonglong2 q1 = *(const ulonglong2*)(col + 128);
            a00 = ffma2(xs, q0.x, a00); a01 = ffma2(xs, q0.y, a01);
            a10 = ffma2(xs, q1.x, a10); a11 = ffma2(xs, q1.y, a11);
        }
        float4 n20 = *(const float4*)&n2b[jt + 4 * lane];
        float4 n21 = *(const float4*)&n2b[jt + 128 + 4 * lane];
        float d[8]; float2 p;
        p = unpack2(a00); d[0] = n20.x - 2.f * p.x; d[1] = n20.y - 2.f * p.y;
        p = unpack2(a01); d[2] = n20.z - 2.f * p.x; d[3] = n20.w - 2.f * p.y;
        p = unpack2(a10); d[4] = n21.x - 2.f * p.x; d[5] = n21.y - 2.f * p.y;
        p = unpack2(a11); d[6] = n21.z - 2.f * p.x; d[7] = n21.w - 2.f * p.y;
        int j0 = jt + 4 * lane;
        #pragma unroll
        for (int q = 0; q < 8; q++) {
            int j = j0 + (q & 3) + ((q >> 2) << 7);
            u64 key = ((u64)encf(d[q]) << 32) | (unsigned)j;
            if (key > lastkey && key < K8[7]) {
                u64 cur = key;
                #pragma unroll
                for (int s = 0; s < 8; s++) {
                    u64 a = K8[s];
                    u64 mn = a < cur ? a : cur;
                    cur = a < cur ? cur : a;
                    K8[s] = mn;
                }
            }
        }
    }
}

// ---------------- kNN: warp-per-row, no smem dist, no inner syncs ----------------
template<int C>
__global__ __launch_bounds__(256) void knn_kernel(const float* __restrict__ xt) {
    __shared__ float sXi[8 * C];
    int tid = threadIdx.x, b = blockIdx.y, i0 = blockIdx.x * 8;
    const float* xb = xt + (size_t)b * C * NP;
    for (int t = tid; t < 8 * C; t += 256) {
        int i = t & 7, c = t >> 3;
        sXi[i * C + c] = xb[(size_t)c * NP + i0 + i];
    }
    __syncthreads();
    int iw = tid >> 5, lane = tid & 31;
    const float* n2b = g_n2 + b * NP;
    const float* xi = sXi + iw * C;

    u64 K8[8];
    #pragma unroll
    for (int q = 0; q < 8; q++) K8[q] = ~0ull;
    knn_scan<C>(xb, xi, n2b, lane, K8, 0ull);

    // extraction: 30 iterations of cross-warp argmin via REDUX
    int gn = b * NP + i0 + iw;
    int cnt = 8; u64 lastkey = 0;
    for (int it = 0; it < KNN; it++) {
        unsigned hv = (unsigned)(K8[0] >> 32);
        unsigned mv = __reduce_min_sync(0xffffffffu, hv);
        unsigned jc = (hv == mv) ? (unsigned)K8[0] : 0xffffffffu;
        unsigned jmin = __reduce_min_sync(0xffffffffu, jc);
        if (hv == mv && (unsigned)K8[0] == jmin) {
            g_idx[gn * KNN + it] = (int)jmin;
            lastkey = K8[0];
            #pragma unroll
            for (int q = 0; q < 7; q++) K8[q] = K8[q + 1];
            K8[7] = ~0ull;
            if (--cnt == 0) {
                // rare: lane exhausted its top-8 — recompute and rescan above lastkey
                #pragma unroll
                for (int q = 0; q < 8; q++) K8[q] = ~0ull;
                knn_scan<C>(xb, xi, n2b, lane, K8, lastkey);
                cnt = 8;
            }
        }
    }
}

// ---------------- fused EdgeConv: 2 nodes/block, two 64x64x64 smem GEMMs + shfl-max ----------------
template<int CIN>
__global__ __launch_bounds__(256)
void edgeconv_kernel(const float* __restrict__ x, int xstride,
                     const float* __restrict__ w0, const float* __restrict__ b0,
                     const float* __restrict__ w1, const float* __restrict__ b1,
                     float* __restrict__ out, int ostride) {
    extern __shared__ float sm[];
    float* sW0 = sm;                   // 2*CIN*64
    float* sW1 = sW0 + 2 * CIN * 64;   // 4096
    float* sB1 = sW1 + 4096;           // 64
    float* sXI = sB1 + 64;             // 128
    float* sA  = sXI + 128;            // 128
    float* sXJ = sA + 128;             // CIN*64  ([c][e])
    float* sH0 = sXJ + CIN * 64;       // 4096    ([u][e])

    int tid = threadIdx.x;
    int gn0 = blockIdx.x * 2;

    for (int t = tid; t < 2 * CIN * 64; t += 256) sW0[t] = w0[t];
    for (int t = tid; t < 4096; t += 256) sW1[t] = w1[t];
    if (tid < 64) sB1[tid] = b1[tid];
    for (int t = tid; t < 2 * CIN; t += 256) {
        int nd = t / CIN, c = t % CIN;
        sXI[nd * 64 + c] = x[(size_t)(gn0 + nd) * xstride + c];
    }
    __syncthreads();
    if (tid < 128) {
        int nd = tid >> 6, t = tid & 63;
        float s = b0[t];
        #pragma unroll
        for (int c = 0; c < CIN; c++)
            s += sXI[nd * 64 + c] * (sW0[c * 64 + t] - sW0[(CIN + c) * 64 + t]);
        sA[nd * 64 + t] = s;
    }
    for (int t = tid; t < 64 * CIN; t += 256) {
        int e = t / CIN, c = t % CIN;
        float v = 0.f;
        if (e < 60) {
            int nd = e / 30, k = e - nd * 30;
            int gn = gn0 + nd, bi = gn >> 11;
            int j = g_idx[gn * KNN + k];
            v = x[((size_t)(bi * NP + j)) * xstride + c];
        }
        sXJ[c * 64 + e] = v;
    }
    __syncthreads();

    int tx = tid & 15, ty = tid >> 4;   // e = 4*tx+i, t = 4*ty+j

    // stage 1 (packed along output channel j)
    u64 acc[4][2] = {};
    #pragma unroll
    for (int c = 0; c < CIN; c++) {
        float4 xv = *(const float4*)&sXJ[c * 64 + 4 * tx];
        ulonglong2 wq = *(const ulonglong2*)&sW0[(CIN + c) * 64 + 4 * ty];
        u64 xp[4] = {splat2(xv.x), splat2(xv.y), splat2(xv.z), splat2(xv.w)};
        #pragma unroll
        for (int i = 0; i < 4; i++) {
            acc[i][0] = ffma2(xp[i], wq.x, acc[i][0]);
            acc[i][1] = ffma2(xp[i], wq.y, acc[i][1]);
        }
    }
    float accf[4][4];
    #pragma unroll
    for (int i = 0; i < 4; i++) {
        float2 l0 = unpack2(acc[i][0]), l1 = unpack2(acc[i][1]);
        accf[i][0] = l0.x; accf[i][1] = l0.y; accf[i][2] = l1.x; accf[i][3] = l1.y;
    }
    #pragma unroll
    for (int j = 0; j < 4; j++) {
        float h[4];
        #pragma unroll
        for (int i = 0; i < 4; i++) {
            int e = 4 * tx + i;
            int nd = (e >= 30) ? 1 : 0;
            float s = accf[i][j] + sA[nd * 64 + 4 * ty + j];
            h[i] = s > 0.f ? s : 0.f;
        }
        *(float4*)&sH0[(4 * ty + j) * 64 + 4 * tx] = make_float4(h[0], h[1], h[2], h[3]);
    }
    __syncthreads();

    // stage 2
    u64 acc2[4][2] = {};
    #pragma unroll
    for (int u = 0; u < 64; u++) {
        float4 xv = *(const float4*)&sH0[u * 64 + 4 * tx];
        ulonglong2 wq = *(const ulonglong2*)&sW1[u * 64 + 4 * ty];
        u64 xp[4] = {splat2(xv.x), splat2(xv.y), splat2(xv.z), splat2(xv.w)};
        #pragma unroll
        for (int i = 0; i < 4; i++) {
            acc2[i][0] = ffma2(xp[i], wq.x, acc2[i][0]);
            acc2[i][1] = ffma2(xp[i], wq.y, acc2[i][1]);
        }
    }
    float acc2f[4][4];
    #pragma unroll
    for (int i = 0; i < 4; i++) {
        float2 l0 = unpack2(acc2[i][0]), l1 = unpack2(acc2[i][1]);
        acc2f[i][0] = l0.x; acc2f[i][1] = l0.y; acc2f[i][2] = l1.x; acc2f[i][3] = l1.y;
    }

    // max over edges (half-warp holds all 64 e's)
    float m[2][4];
    #pragma unroll
    for (int nd = 0; nd < 2; nd++)
        #pragma unroll
        for (int j = 0; j < 4; j++) m[nd][j] = -3.4e38f;
    #pragma unroll
    for (int i = 0; i < 4; i++) {
        int e = 4 * tx + i;
        if (e < 60) {
            int nd = (e >= 30) ? 1 : 0;
            #pragma unroll
            for (int j = 0; j < 4; j++) m[nd][j] = fmaxf(m[nd][j], acc2f[i][j]);
        }
    }
    #pragma unroll
    for (int o = 8; o >= 1; o >>= 1) {
        #pragma unroll
        for (int nd = 0; nd < 2; nd++)
            #pragma unroll
            for (int j = 0; j < 4; j++)
                m[nd][j] = fmaxf(m[nd][j], __shfl_down_sync(0xffffffffu, m[nd][j], o, 16));
    }
    if (tx == 0) {
        #pragma unroll
        for (int nd = 0; nd < 2; nd++)
            #pragma unroll
            for (int j = 0; j < 4; j++)
                out[(size_t)(gn0 + nd) * ostride + 4 * ty + j] = m[nd][j] + sB1[4 * ty + j];
    }
}

// ---------------- SGEMM: C[M,N] = relu?(A[M,K] @ W[K,N] + bias) ----------------
// 128x128 block tile, 256 threads, 8x8 microtile, f32x2 packed FMA.
__global__ __launch_bounds__(256)
void sgemm_kernel(const float* __restrict__ A, const float* __restrict__ W,
                  const float* __restrict__ bias, float* __restrict__ C,
                  int M, int Nn, int Kk, int relu) {
    __shared__ float As[16 * 128];
    __shared__ float Bs[16 * 128];
    int tid = threadIdx.x;
    int m0 = blockIdx.y * 128, n0 = blockIdx.x * 128;
    int tx = tid & 15, ty = tid >> 4;
    u64 acc[8][4] = {};
    for (int k0 = 0; k0 < Kk; k0 += 16) {
        #pragma unroll
        for (int q = 0; q < 2; q++) {
            int fi = tid + 256 * q;
            int row = fi >> 2, kq = fi & 3;
            float4 a = *(const float4*)&A[(size_t)(m0 + row) * Kk + k0 + 4 * kq];
            As[(4 * kq + 0) * 128 + row] = a.x;
            As[(4 * kq + 1) * 128 + row] = a.y;
            As[(4 * kq + 2) * 128 + row] = a.z;
            As[(4 * kq + 3) * 128 + row] = a.w;
        }
        #pragma unroll
        for (int q = 0; q < 2; q++) {
            int fi = tid + 256 * q;
            int k = fi >> 5, nq = fi & 31;
            *(float4*)&Bs[k * 128 + 4 * nq] =
                *(const float4*)&W[(size_t)(k0 + k) * Nn + n0 + 4 * nq];
        }
        __syncthreads();
        #pragma unroll
        for (int kk = 0; kk < 16; kk++) {
            float4 a0 = *(const float4*)&As[kk * 128 + 8 * ty];
            float4 a1 = *(const float4*)&As[kk * 128 + 8 * ty + 4];
            ulonglong2 bq0 = *(const ulonglong2*)&Bs[kk * 128 + 8 * tx];
            ulonglong2 bq1 = *(const ulonglong2*)&Bs[kk * 128 + 8 * tx + 4];
            u64 bp[4] = {bq0.x, bq0.y, bq1.x, bq1.y};
            u64 ap[8] = {splat2(a0.x), splat2(a0.y), splat2(a0.z), splat2(a0.w),
                         splat2(a1.x), splat2(a1.y), splat2(a1.z), splat2(a1.w)};
            #pragma unroll
            for (int i = 0; i < 8; i++)
                #pragma unroll
                for (int jp = 0; jp < 4; jp++)
                    acc[i][jp] = ffma2(ap[i], bp[jp], acc[i][jp]);
        }
        __syncthreads();
    }
    float4 bv0 = *(const float4*)&bias[n0 + 8 * tx];
    float4 bv1 = *(const float4*)&bias[n0 + 8 * tx + 4];
    float bb[8] = {bv0.x, bv0.y, bv0.z, bv0.w, bv1.x, bv1.y, bv1.z, bv1.w};
    #pragma unroll
    for (int i = 0; i < 8; i++) {
        float o[8];
        #pragma unroll
        for (int jp = 0; jp < 4; jp++) {
            float2 l = unpack2(acc[i][jp]);
            o[2 * jp] = l.x; o[2 * jp + 1] = l.y;
        }
        #pragma unroll
        for (int j = 0; j < 8; j++) {
            float v = o[j] + bb[j];
            o[j] = (relu && v < 0.f) ? 0.f : v;
        }
        *(float4*)&C[(size_t)(m0 + 8 * ty + i) * Nn + n0 + 8 * tx] =
            make_float4(o[0], o[1], o[2], o[3]);
        *(float4*)&C[(size_t)(m0 + 8 * ty + i) * Nn + n0 + 8 * tx + 4] =
            make_float4(o[4], o[5], o[6], o[7]);
    }
}

// ---------------- final head: out[m,0:3] = h3[m,:] @ fin_w + fin_b ----------------
__global__ void fin_kernel(const float* __restrict__ h3, const float* __restrict__ w,
                           const float* __restrict__ bb, float* __restrict__ out) {
    __shared__ float sw[128 * 3];
    __shared__ float sb[3];
    int tid = threadIdx.x;
    for (int t = tid; t < 384; t += 256) sw[t] = w[t];
    if (tid < 3) sb[tid] = bb[tid];
    __syncthreads();
    int m = blockIdx.x * 256 + tid;
    const float* row = h3 + (size_t)m * 128;
    float s0 = sb[0], s1 = sb[1], s2 = sb[2];
    #pragma unroll 8
    for (int c = 0; c < 128; c++) {
        float v = row[c];
        s0 += v * sw[c * 3 + 0];
        s1 += v * sw[c * 3 + 1];
        s2 += v * sw[c * 3 + 2];
    }
    out[m * 3 + 0] = s0;
    out[m * 3 + 1] = s1;
    out[m * 3 + 2] = s2;
}

// ---------------- launch ----------------
extern "C" void kernel_launch(void* const* d_in, const int* in_sizes, int n_in,
                              void* d_out, int out_size) {
    const float* pos    = (const float*)d_in[0];
    const float* c1_w0  = (const float*)d_in[1];
    const float* c1_b0  = (const float*)d_in[2];
    const float* c1_w1  = (const float*)d_in[3];
    const float* c1_b1  = (const float*)d_in[4];
    const float* c2_w0  = (const float*)d_in[5];
    const float* c2_b0  = (const float*)d_in[6];
    const float* c2_w1  = (const float*)d_in[7];
    const float* c2_b1  = (const float*)d_in[8];
    const float* c3_w0  = (const float*)d_in[9];
    const float* c3_b0  = (const float*)d_in[10];
    const float* c3_w1  = (const float*)d_in[11];
    const float* c3_b1  = (const float*)d_in[12];
    const float* mlp_w0 = (const float*)d_in[13];
    const float* mlp_b0 = (const float*)d_in[14];
    const float* mlp_w1 = (const float*)d_in[15];
    const float* mlp_b1 = (const float*)d_in[16];
    const float* mlp_w2 = (const float*)d_in[17];
    const float* mlp_b2 = (const float*)d_in[18];
    const float* fin_w  = (const float*)d_in[19];
    const float* fin_b  = (const float*)d_in[20];

    float *feat, *h1, *h2, *h3, *xt;
    cudaGetSymbolAddress((void**)&feat, g_feat);
    cudaGetSymbolAddress((void**)&h1, g_h1);
    cudaGetSymbolAddress((void**)&h2, g_h2);
    cudaGetSymbolAddress((void**)&h3, g_h3);
    cudaGetSymbolAddress((void**)&xt, g_xt);

    const int smemEC3  = (2 * 3 * 64 + 4096 + 64 + 128 + 128 + 3 * 64 + 4096) * 4;
    const int smemEC64 = (2 * 64 * 64 + 4096 + 64 + 128 + 128 + 64 * 64 + 4096) * 4;
    cudaFuncSetAttribute(edgeconv_kernel<3>,  cudaFuncAttributeMaxDynamicSharedMemorySize, smemEC3);
    cudaFuncSetAttribute(edgeconv_kernel<64>, cudaFuncAttributeMaxDynamicSharedMemorySize, smemEC64);

    dim3 kgrid(NP / 8, BB);
    dim3 xgrid(NP / 32, BB);

    // ---- conv1 (pos, C=3) -> feat[:, 0:64]
    xpose3_kernel<<<NN / 256, 256>>>(pos, xt);
    knn_kernel<3><<<kgrid, 256>>>(xt);
    edgeconv_kernel<3><<<NN / 2, 256, smemEC3>>>(pos, 3, c1_w0, c1_b0, c1_w1, c1_b1, feat + 0, 192);

    // ---- conv2 (x1, C=64) -> feat[:, 64:128]
    xpose64_kernel<<<xgrid, 256>>>(feat, 192, xt);
    knn_kernel<64><<<kgrid, 256>>>(xt);
    edgeconv_kernel<64><<<NN / 2, 256, smemEC64>>>(feat, 192, c2_w0, c2_b0, c2_w1, c2_b1, feat + 64, 192);

    // ---- conv3 (x2, C=64) -> feat[:, 128:192]
    xpose64_kernel<<<xgrid, 256>>>(feat + 64, 192, xt);
    knn_kernel<64><<<kgrid, 256>>>(xt);
    edgeconv_kernel<64><<<NN / 2, 256, smemEC64>>>(feat + 64, 192, c3_w0, c3_b0, c3_w1, c3_b1, feat + 128, 192);

    // ---- MLP
    sgemm_kernel<<<dim3(1024 / 128, NN / 128), 256>>>(feat, mlp_w0, mlp_b0, h1, NN, 1024, 192, 1);
    sgemm_kernel<<<dim3(256 / 128, NN / 128), 256>>>(h1, mlp_w1, mlp_b1, h2, NN, 256, 1024, 1);
    sgemm_kernel<<<dim3(128 / 128, NN / 128), 256>>>(h2, mlp_w2, mlp_b2, h3, NN, 128, 256, 0);
    fin_kernel<<<NN / 256, 256>>>(h3, fin_w, fin_b, (float*)d_out);
}

// round 8
// speedup vs baseline: 2.1703x; 1.4281x over previous
#include <cuda_runtime.h>
#include <cstdint>

#define BB 16
#define NP 2048
#define NN (BB*NP)   // 32768 total nodes
#define KNN 30

typedef unsigned long long u64;

// ---------------- scratch (device globals; no cudaMalloc allowed) ----------------
__device__ int   g_idx[NN * KNN];           // kNN indices (within batch)
__device__ float g_n2[NN];                  // squared norms
__device__ float g_xt[BB * 64 * NP];        // transposed features [b][c][j]
__device__ float g_P[NN * 64];              // x_j @ W0_bot per node
__device__ float g_A[NN * 64];              // b0 + x_i@W0_top - P[i]
__device__ float g_feat[NN * 192];          // concat [x1 | x2 | x3]
__device__ float g_h1[NN * 1024];
__device__ float g_h2[NN * 256];
__device__ float g_h3[NN * 128];

// ---------------- helpers ----------------
__device__ __forceinline__ unsigned encf(float f) {
    unsigned u = __float_as_uint(f);
    return (u & 0x80000000u) ? ~u : (u | 0x80000000u);
}
// packed fp32x2 (sm_100+): one instruction, two exact fp32 FMAs
__device__ __forceinline__ u64 splat2(float v) {
    u64 r; asm("mov.b64 %0, {%1, %1};" : "=l"(r) : "f"(v)); return r;
}
__device__ __forceinline__ u64 ffma2(u64 a, u64 b, u64 c) {
    u64 d; asm("fma.rn.f32x2 %0, %1, %2, %3;" : "=l"(d) : "l"(a), "l"(b), "l"(c)); return d;
}
__device__ __forceinline__ float2 unpack2(u64 v) {
    float2 r; asm("mov.b64 {%0, %1}, %2;" : "=f"(r.x), "=f"(r.y) : "l"(v)); return r;
}

// ---------------- transpose (+ squared norms) ----------------
__global__ void xpose3_kernel(const float* __restrict__ x, float* __restrict__ xt) {
    int g = blockIdx.x * blockDim.x + threadIdx.x;
    if (g < NN) {
        int b = g >> 11, j = g & (NP - 1);
        float a = x[g * 3], bv = x[g * 3 + 1], c = x[g * 3 + 2];
        float* xtb = xt + (size_t)b * 3 * NP;
        xtb[j] = a; xtb[NP + j] = bv; xtb[2 * NP + j] = c;
        float s = 0.f; s += a * a; s += bv * bv; s += c * c;
        g_n2[g] = s;
    }
}

__global__ __launch_bounds__(256)
void xpose64_kernel(const float* __restrict__ x, int stride, float* __restrict__ xt) {
    __shared__ float s[32][65];
    int b = blockIdx.y, j0 = blockIdx.x * 32, tid = threadIdx.x;
    const float* xb = x + (size_t)b * NP * stride;
    for (int t = tid; t < 32 * 64; t += 256) {
        int j = t >> 6, c = t & 63;
        s[j][c] = xb[(size_t)(j0 + j) * stride + c];
    }
    __syncthreads();
    float* xtb = xt + (size_t)b * 64 * NP;
    for (int t = tid; t < 32 * 64; t += 256) {
        int c = t >> 5, j = t & 31;
        xtb[(size_t)c * NP + j0 + j] = s[j][c];
    }
    if (tid < 32) {
        float acc = 0.f;
        #pragma unroll
        for (int c = 0; c < 64; c++) { float v = s[tid][c]; acc += v * v; }
        g_n2[b * NP + j0 + tid] = acc;
    }
}

// ---------------- fused dist + select scan ----------------
template<int C>
__device__ __forceinline__ void knn_scan(const float* __restrict__ xb,
                                         const float* __restrict__ xi,
                                         const float* __restrict__ n2b,
                                         int lane, u64* K8, u64 lastkey) {
    for (int jt = 0; jt < NP; jt += 256) {
        u64 a00 = 0ull, a01 = 0ull, a10 = 0ull, a11 = 0ull;
        #pragma unroll
        for (int c = 0; c < C; c++) {
            u64 xs = splat2(xi[c]);
            const float* col = xb + (size_t)c * NP + jt + 4 * lane;
            ulonglong2 q0 = *(const ulonglong2*)col;
            ulonglong2 q1 = *(const ulonglong2*)(col + 128);
            a00 = ffma2(xs, q0.x, a00); a01 = ffma2(xs, q0.y, a01);
            a10 = ffma2(xs, q1.x, a10); a11 = ffma2(xs, q1.y, a11);
        }
        float4 n20 = *(const float4*)&n2b[jt + 4 * lane];
        float4 n21 = *(const float4*)&n2b[jt + 128 + 4 * lane];
        float d[8]; float2 p;
        p = unpack2(a00); d[0] = n20.x - 2.f * p.x; d[1] = n20.y - 2.f * p.y;
        p = unpack2(a01); d[2] = n20.z - 2.f * p.x; d[3] = n20.w - 2.f * p.y;
        p = unpack2(a10); d[4] = n21.x - 2.f * p.x; d[5] = n21.y - 2.f * p.y;
        p = unpack2(a11); d[6] = n21.z - 2.f * p.x; d[7] = n21.w - 2.f * p.y;
        int j0 = jt + 4 * lane;
        #pragma unroll
        for (int q = 0; q < 8; q++) {
            int j = j0 + (q & 3) + ((q >> 2) << 7);
            u64 key = ((u64)encf(d[q]) << 32) | (unsigned)j;
            if (key > lastkey && key < K8[7]) {
                u64 cur = key;
                #pragma unroll
                for (int s = 0; s < 8; s++) {
                    u64 a = K8[s];
                    u64 mn = a < cur ? a : cur;
                    cur = a < cur ? cur : a;
                    K8[s] = mn;
                }
            }
        }
    }
}

// ---------------- kNN: warp-per-row, no smem dist, no inner syncs ----------------
template<int C>
__global__ __launch_bounds__(256) void knn_kernel(const float* __restrict__ xt) {
    __shared__ float sXi[8 * C];
    int tid = threadIdx.x, b = blockIdx.y, i0 = blockIdx.x * 8;
    const float* xb = xt + (size_t)b * C * NP;
    for (int t = tid; t < 8 * C; t += 256) {
        int i = t & 7, c = t >> 3;
        sXi[i * C + c] = xb[(size_t)c * NP + i0 + i];
    }
    __syncthreads();
    int iw = tid >> 5, lane = tid & 31;
    const float* n2b = g_n2 + b * NP;
    const float* xi = sXi + iw * C;

    u64 K8[8];
    #pragma unroll
    for (int q = 0; q < 8; q++) K8[q] = ~0ull;
    knn_scan<C>(xb, xi, n2b, lane, K8, 0ull);

    int gn = b * NP + i0 + iw;
    int cnt = 8; u64 lastkey = 0;
    for (int it = 0; it < KNN; it++) {
        unsigned hv = (unsigned)(K8[0] >> 32);
        unsigned mv = __reduce_min_sync(0xffffffffu, hv);
        unsigned jc = (hv == mv) ? (unsigned)K8[0] : 0xffffffffu;
        unsigned jmin = __reduce_min_sync(0xffffffffu, jc);
        if (hv == mv && (unsigned)K8[0] == jmin) {
            g_idx[gn * KNN + it] = (int)jmin;
            lastkey = K8[0];
            #pragma unroll
            for (int q = 0; q < 7; q++) K8[q] = K8[q + 1];
            K8[7] = ~0ull;
            if (--cnt == 0) {
                #pragma unroll
                for (int q = 0; q < 8; q++) K8[q] = ~0ull;
                knn_scan<C>(xb, xi, n2b, lane, K8, lastkey);
                cnt = 8;
            }
        }
    }
}

// ---------------- prep: P[i] = x_i @ W0_bot,  A[i] = b0 + x_i @ W0_top - P[i] ----------------
// 32 nodes/block, node-per-lane, 8 out channels per thread (tid>>5).
template<int CIN>
__global__ __launch_bounds__(256)
void prep_kernel(const float* __restrict__ x, int xstride,
                 const float* __restrict__ w0, const float* __restrict__ b0,
                 float* __restrict__ P, float* __restrict__ A) {
    __shared__ float sX[32][CIN + 1];
    __shared__ float sW[2 * CIN * 64];
    __shared__ float sB0[64];
    int tid = threadIdx.x, n0 = blockIdx.x * 32;
    for (int t = tid; t < 2 * CIN * 64; t += 256) sW[t] = w0[t];
    if (tid < 64) sB0[tid] = b0[tid];
    for (int t = tid; t < 32 * CIN; t += 256) {
        int n = t / CIN, c = t % CIN;
        sX[n][c] = x[(size_t)(n0 + n) * xstride + c];
    }
    __syncthreads();
    int n = tid & 31, og = tid >> 3 & 0x18;  // og = (tid>>5)*8... compute directly:
    og = (tid >> 5) * 8;
    u64 accU[4] = {}, accP[4] = {};
    #pragma unroll
    for (int c = 0; c < CIN; c++) {
        u64 xs = splat2(sX[n][c]);
        ulonglong2 wt0 = *(const ulonglong2*)&sW[c * 64 + og];
        ulonglong2 wt1 = *(const ulonglong2*)&sW[c * 64 + og + 4];
        ulonglong2 wb0 = *(const ulonglong2*)&sW[(CIN + c) * 64 + og];
        ulonglong2 wb1 = *(const ulonglong2*)&sW[(CIN + c) * 64 + og + 4];
        accU[0] = ffma2(xs, wt0.x, accU[0]); accU[1] = ffma2(xs, wt0.y, accU[1]);
        accU[2] = ffma2(xs, wt1.x, accU[2]); accU[3] = ffma2(xs, wt1.y, accU[3]);
        accP[0] = ffma2(xs, wb0.x, accP[0]); accP[1] = ffma2(xs, wb0.y, accP[1]);
        accP[2] = ffma2(xs, wb1.x, accP[2]); accP[3] = ffma2(xs, wb1.y, accP[3]);
    }
    float pv[8], av[8];
    #pragma unroll
    for (int q = 0; q < 4; q++) {
        float2 pu = unpack2(accP[q]), uu = unpack2(accU[q]);
        pv[2 * q] = pu.x; pv[2 * q + 1] = pu.y;
        av[2 * q] = sB0[og + 2 * q] + uu.x - pu.x;
        av[2 * q + 1] = sB0[og + 2 * q + 1] + uu.y - pu.y;
    }
    size_t base = (size_t)(n0 + n) * 64 + og;
    *(float4*)&P[base] = make_float4(pv[0], pv[1], pv[2], pv[3]);
    *(float4*)&P[base + 4] = make_float4(pv[4], pv[5], pv[6], pv[7]);
    *(float4*)&A[base] = make_float4(av[0], av[1], av[2], av[3]);
    *(float4*)&A[base + 4] = make_float4(av[4], av[5], av[6], av[7]);
}

// ---------------- EdgeConv stage2: 8 nodes/block, 256x64x64 GEMM + shfl-max ----------------
// h0[c][e] = relu(A[nd][c] + P[j_e][c]) built by gather; out = max_e(h0 @ W1) + b1.
// Edges padded to 32/node (k_eff = min(k,29): duplicate of a valid edge, max-invariant).
__global__ __launch_bounds__(256)
void edgeconv8_kernel(const float* __restrict__ P, const float* __restrict__ A,
                      const float* __restrict__ w1, const float* __restrict__ b1,
                      float* __restrict__ out, int ostride) {
    extern __shared__ float sm[];
    float* sW1 = sm;            // 4096
    float* sA  = sW1 + 4096;    // 512
    float* sB1 = sA + 512;      // 64
    int*   sJ  = (int*)(sB1 + 64);   // 256
    float* sH  = (float*)(sJ + 256); // 64*256

    int tid = threadIdx.x;
    int gn0 = blockIdx.x * 8;
    int bbase = (gn0 >> 11) << 11;   // batch * NP

    for (int t = tid; t < 4096; t += 256) sW1[t] = w1[t];
    for (int t = tid; t < 512; t += 256) sA[t] = A[(size_t)gn0 * 64 + t];
    if (tid < 64) sB1[tid] = b1[tid];
    {
        int nd = tid >> 5, k = tid & 31;
        if (k > 29) k = 29;
        sJ[tid] = bbase + g_idx[(gn0 + nd) * KNN + k];
    }
    __syncthreads();

    // gather + relu: 4096 float4 units, t = q*256 + e (q = c/4)
    #pragma unroll
    for (int it = 0; it < 16; it++) {
        int e = tid;
        int q = it;
        int j = sJ[e];
        int nd = e >> 5;
        float4 p4 = *(const float4*)&P[(size_t)j * 64 + 4 * q];
        float4 a4 = *(const float4*)&sA[nd * 64 + 4 * q];
        float h0 = a4.x + p4.x, h1v = a4.y + p4.y, h2v = a4.z + p4.z, h3v = a4.w + p4.w;
        sH[(4 * q + 0) * 256 + e] = h0 > 0.f ? h0 : 0.f;
        sH[(4 * q + 1) * 256 + e] = h1v > 0.f ? h1v : 0.f;
        sH[(4 * q + 2) * 256 + e] = h2v > 0.f ? h2v : 0.f;
        sH[(4 * q + 3) * 256 + e] = h3v > 0.f ? h3v : 0.f;
    }
    __syncthreads();

    int tx = tid & 31, ty = tid >> 5;   // edges {4tx..}+{128+4tx..}, out 8*ty..

    u64 acc[8][4] = {};
    #pragma unroll
    for (int c = 0; c < 64; c++) {
        float4 e0 = *(const float4*)&sH[c * 256 + 4 * tx];
        float4 e1 = *(const float4*)&sH[c * 256 + 128 + 4 * tx];
        ulonglong2 wq0 = *(const ulonglong2*)&sW1[c * 64 + 8 * ty];
        ulonglong2 wq1 = *(const ulonglong2*)&sW1[c * 64 + 8 * ty + 4];
        u64 wp[4] = {wq0.x, wq0.y, wq1.x, wq1.y};
        u64 ep[8] = {splat2(e0.x), splat2(e0.y), splat2(e0.z), splat2(e0.w),
                     splat2(e1.x), splat2(e1.y), splat2(e1.z), splat2(e1.w)};
        #pragma unroll
        for (int i = 0; i < 8; i++)
            #pragma unroll
            for (int jp = 0; jp < 4; jp++)
                acc[i][jp] = ffma2(ep[i], wp[jp], acc[i][jp]);
    }

    // per-thread max over its 4 edges of each node group
    float m1[8], m2[8];
    #pragma unroll
    for (int j = 0; j < 8; j++) { m1[j] = -3.4e38f; m2[j] = -3.4e38f; }
    #pragma unroll
    for (int i = 0; i < 4; i++) {
        #pragma unroll
        for (int jp = 0; jp < 4; jp++) {
            float2 l = unpack2(acc[i][jp]);
            m1[2 * jp] = fmaxf(m1[2 * jp], l.x);
            m1[2 * jp + 1] = fmaxf(m1[2 * jp + 1], l.y);
        }
    }
    #pragma unroll
    for (int i = 4; i < 8; i++) {
        #pragma unroll
        for (int jp = 0; jp < 4; jp++) {
            float2 l = unpack2(acc[i][jp]);
            m2[2 * jp] = fmaxf(m2[2 * jp], l.x);
            m2[2 * jp + 1] = fmaxf(m2[2 * jp + 1], l.y);
        }
    }
    // reduce across 8 lanes (one node's 32 edges)
    #pragma unroll
    for (int o = 4; o >= 1; o >>= 1) {
        #pragma unroll
        for (int j = 0; j < 8; j++) {
            m1[j] = fmaxf(m1[j], __shfl_down_sync(0xffffffffu, m1[j], o, 8));
            m2[j] = fmaxf(m2[j], __shfl_down_sync(0xffffffffu, m2[j], o, 8));
        }
    }
    if ((tx & 7) == 0) {
        int n1 = tx >> 3, n2 = 4 + (tx >> 3);
        float o1[8], o2[8];
        #pragma unroll
        for (int j = 0; j < 8; j++) {
            o1[j] = m1[j] + sB1[8 * ty + j];
            o2[j] = m2[j] + sB1[8 * ty + j];
        }
        float* d1 = &out[(size_t)(gn0 + n1) * ostride + 8 * ty];
        float* d2 = &out[(size_t)(gn0 + n2) * ostride + 8 * ty];
        *(float4*)d1 = make_float4(o1[0], o1[1], o1[2], o1[3]);
        *(float4*)(d1 + 4) = make_float4(o1[4], o1[5], o1[6], o1[7]);
        *(float4*)d2 = make_float4(o2[0], o2[1], o2[2], o2[3]);
        *(float4*)(d2 + 4) = make_float4(o2[4], o2[5], o2[6], o2[7]);
    }
}

// ---------------- SGEMM: C[M,N] = relu?(A[M,K] @ W[K,N] + bias) ----------------
__global__ __launch_bounds__(256)
void sgemm_kernel(const float* __restrict__ A, const float* __restrict__ W,
                  const float* __restrict__ bias, float* __restrict__ C,
                  int M, int Nn, int Kk, int relu) {
    __shared__ float As[16 * 128];
    __shared__ float Bs[16 * 128];
    int tid = threadIdx.x;
    int m0 = blockIdx.y * 128, n0 = blockIdx.x * 128;
    int tx = tid & 15, ty = tid >> 4;
    u64 acc[8][4] = {};
    for (int k0 = 0; k0 < Kk; k0 += 16) {
        #pragma unroll
        for (int q = 0; q < 2; q++) {
            int fi = tid + 256 * q;
            int row = fi >> 2, kq = fi & 3;
            float4 a = *(const float4*)&A[(size_t)(m0 + row) * Kk + k0 + 4 * kq];
            As[(4 * kq + 0) * 128 + row] = a.x;
            As[(4 * kq + 1) * 128 + row] = a.y;
            As[(4 * kq + 2) * 128 + row] = a.z;
            As[(4 * kq + 3) * 128 + row] = a.w;
        }
        #pragma unroll
        for (int q = 0; q < 2; q++) {
            int fi = tid + 256 * q;
            int k = fi >> 5, nq = fi & 31;
            *(float4*)&Bs[k * 128 + 4 * nq] =
                *(const float4*)&W[(size_t)(k0 + k) * Nn + n0 + 4 * nq];
        }
        __syncthreads();
        #pragma unroll
        for (int kk = 0; kk < 16; kk++) {
            float4 a0 = *(const float4*)&As[kk * 128 + 8 * ty];
            float4 a1 = *(const float4*)&As[kk * 128 + 8 * ty + 4];
            ulonglong2 bq0 = *(const ulonglong2*)&Bs[kk * 128 + 8 * tx];
            ulonglong2 bq1 = *(const ulonglong2*)&Bs[kk * 128 + 8 * tx + 4];
            u64 bp[4] = {bq0.x, bq0.y, bq1.x, bq1.y};
            u64 ap[8] = {splat2(a0.x), splat2(a0.y), splat2(a0.z), splat2(a0.w),
                         splat2(a1.x), splat2(a1.y), splat2(a1.z), splat2(a1.w)};
            #pragma unroll
            for (int i = 0; i < 8; i++)
                #pragma unroll
                for (int jp = 0; jp < 4; jp++)
                    acc[i][jp] = ffma2(ap[i], bp[jp], acc[i][jp]);
        }
        __syncthreads();
    }
    float4 bv0 = *(const float4*)&bias[n0 + 8 * tx];
    float4 bv1 = *(const float4*)&bias[n0 + 8 * tx + 4];
    float bb[8] = {bv0.x, bv0.y, bv0.z, bv0.w, bv1.x, bv1.y, bv1.z, bv1.w};
    #pragma unroll
    for (int i = 0; i < 8; i++) {
        float o[8];
        #pragma unroll
        for (int jp = 0; jp < 4; jp++) {
            float2 l = unpack2(acc[i][jp]);
            o[2 * jp] = l.x; o[2 * jp + 1] = l.y;
        }
        #pragma unroll
        for (int j = 0; j < 8; j++) {
            float v = o[j] + bb[j];
            o[j] = (relu && v < 0.f) ? 0.f : v;
        }
        *(float4*)&C[(size_t)(m0 + 8 * ty + i) * Nn + n0 + 8 * tx] =
            make_float4(o[0], o[1], o[2], o[3]);
        *(float4*)&C[(size_t)(m0 + 8 * ty + i) * Nn + n0 + 8 * tx + 4] =
            make_float4(o[4], o[5], o[6], o[7]);
    }
}

// ---------------- final head ----------------
__global__ void fin_kernel(const float* __restrict__ h3, const float* __restrict__ w,
                           const float* __restrict__ bb, float* __restrict__ out) {
    __shared__ float sw[128 * 3];
    __shared__ float sb[3];
    int tid = threadIdx.x;
    for (int t = tid; t < 384; t += 256) sw[t] = w[t];
    if (tid < 3) sb[tid] = bb[tid];
    __syncthreads();
    int m = blockIdx.x * 256 + tid;
    const float* row = h3 + (size_t)m * 128;
    float s0 = sb[0], s1 = sb[1], s2 = sb[2];
    #pragma unroll 8
    for (int c = 0; c < 128; c++) {
        float v = row[c];
        s0 += v * sw[c * 3 + 0];
        s1 += v * sw[c * 3 + 1];
        s2 += v * sw[c * 3 + 2];
    }
    out[m * 3 + 0] = s0;
    out[m * 3 + 1] = s1;
    out[m * 3 + 2] = s2;
}

// ---------------- launch ----------------
extern "C" void kernel_launch(void* const* d_in, const int* in_sizes, int n_in,
                              void* d_out, int out_size) {
    const float* pos    = (const float*)d_in[0];
    const float* c1_w0  = (const float*)d_in[1];
    const float* c1_b0  = (const float*)d_in[2];
    const float* c1_w1  = (const float*)d_in[3];
    const float* c1_b1  = (const float*)d_in[4];
    const float* c2_w0  = (const float*)d_in[5];
    const float* c2_b0  = (const float*)d_in[6];
    const float* c2_w1  = (const float*)d_in[7];
    const float* c2_b1  = (const float*)d_in[8];
    const float* c3_w0  = (const float*)d_in[9];
    const float* c3_b0  = (const float*)d_in[10];
    const float* c3_w1  = (const float*)d_in[11];
    const float* c3_b1  = (const float*)d_in[12];
    const float* mlp_w0 = (const float*)d_in[13];
    const float* mlp_b0 = (const float*)d_in[14];
    const float* mlp_w1 = (const float*)d_in[15];
    const float* mlp_b1 = (const float*)d_in[16];
    const float* mlp_w2 = (const float*)d_in[17];
    const float* mlp_b2 = (const float*)d_in[18];
    const float* fin_w  = (const float*)d_in[19];
    const float* fin_b  = (const float*)d_in[20];

    float *feat, *h1, *h2, *h3, *xt, *Pp, *Ap;
    cudaGetSymbolAddress((void**)&feat, g_feat);
    cudaGetSymbolAddress((void**)&h1, g_h1);
    cudaGetSymbolAddress((void**)&h2, g_h2);
    cudaGetSymbolAddress((void**)&h3, g_h3);
    cudaGetSymbolAddress((void**)&xt, g_xt);
    cudaGetSymbolAddress((void**)&Pp, g_P);
    cudaGetSymbolAddress((void**)&Ap, g_A);

    const int smemEC8 = (4096 + 512 + 64 + 256 + 64 * 256) * 4;  // ~85.3 KB
    cudaFuncSetAttribute(edgeconv8_kernel, cudaFuncAttributeMaxDynamicSharedMemorySize, smemEC8);

    dim3 kgrid(NP / 8, BB);
    dim3 xgrid(NP / 32, BB);

    // ---- conv1 (pos, C=3) -> feat[:, 0:64]
    xpose3_kernel<<<NN / 256, 256>>>(pos, xt);
    knn_kernel<3><<<kgrid, 256>>>(xt);
    prep_kernel<3><<<NN / 32, 256>>>(pos, 3, c1_w0, c1_b0, Pp, Ap);
    edgeconv8_kernel<<<NN / 8, 256, smemEC8>>>(Pp, Ap, c1_w1, c1_b1, feat + 0, 192);

    // ---- conv2 (x1, C=64) -> feat[:, 64:128]
    xpose64_kernel<<<xgrid, 256>>>(feat, 192, xt);
    knn_kernel<64><<<kgrid, 256>>>(xt);
    prep_kernel<64><<<NN / 32, 256>>>(feat, 192, c2_w0, c2_b0, Pp, Ap);
    edgeconv8_kernel<<<NN / 8, 256, smemEC8>>>(Pp, Ap, c2_w1, c2_b1, feat + 64, 192);

    // ---- conv3 (x2, C=64) -> feat[:, 128:192]
    xpose64_kernel<<<xgrid, 256>>>(feat + 64, 192, xt);
    knn_kernel<64><<<kgrid, 256>>>(xt);
    prep_kernel<64><<<NN / 32, 256>>>(feat + 64, 192, c3_w0, c3_b0, Pp, Ap);
    edgeconv8_kernel<<<NN / 8, 256, smemEC8>>>(Pp, Ap, c3_w1, c3_b1, feat + 128, 192);

    // ---- MLP
    sgemm_kernel<<<dim3(1024 / 128, NN / 128), 256>>>(feat, mlp_w0, mlp_b0, h1, NN, 1024, 192, 1);
    sgemm_kernel<<<dim3(256 / 128, NN / 128), 256>>>(h1, mlp_w1, mlp_b1, h2, NN, 256, 1024, 1);
    sgemm_kernel<<<dim3(128 / 128, NN / 128), 256>>>(h2, mlp_w2, mlp_b2, h3, NN, 128, 256, 0);
    fin_kernel<<<NN / 256, 256>>>(h3, fin_w, fin_b, (float*)d_out);
}